// round 4
// baseline (speedup 1.0000x reference)
#include <cuda_runtime.h>
#include <cuda_bf16.h>
#include <math.h>
#include <stdint.h>

// Problem constants
#define NTOK 16384
#define DM   512
#define RHM  1024
#define HM   2048
#define EM   8
#define TOPK 4

// GEMM tile config
#define BM 128
#define BN 256
#define BK 32
#define STAGES 3
#define ROWB 80                         // 64B data + 16B pad per K-row
#define SA_BYTES (128 * ROWB)           // 10240
#define SB_BYTES (256 * ROWB)           // 20480
#define STG_BYTES (2 * SA_BYTES + 2 * SB_BYTES)   // 61440
#define SMEM_DYN (STAGES * STG_BYTES)   // 184320

// out modes
#define OUT_SPLIT 0
#define OUT_F32   1
#define OUT_SCAT  2

typedef __nv_bfloat16 bf16;

// ---------------- scratch (static device globals) ---------------------------
__device__ bf16  g_xh[(size_t)NTOK * DM];
__device__ bf16  g_xl[(size_t)NTOK * DM];
__device__ bf16  g_b1h[(size_t)NTOK * HM];
__device__ bf16  g_b1l[(size_t)NTOK * HM];
__device__ bf16  g_b2h[(size_t)NTOK * HM];
__device__ bf16  g_b2l[(size_t)NTOK * HM];
__device__ bf16  g_b3h[(size_t)NTOK * HM];
__device__ bf16  g_b3l[(size_t)NTOK * HM];
__device__ float g_f32[(size_t)NTOK * RHM];
__device__ float g_logits[(size_t)NTOK * EM];
__device__ unsigned g_maskb[NTOK];
__device__ int   g_idx[EM * NTOK];
__device__ int   g_cnt[EM];
// K-major bf16 hi/lo weight copies
#define WT_RIN  0L
#define WT_RS1  (WT_RIN + 512L * 1024L)
#define WT_RS2  (WT_RS1 + 1024L * 1024L)
#define WT_RS3  (WT_RS2 + 1024L * 1024L)
#define WT_EIN  (WT_RS3 + 1024L * 1024L)
#define WT_ES1  (WT_EIN + 8L * 512L * 2048L)
#define WT_ES2  (WT_ES1 + 8L * 2048L * 2048L)
#define WT_ES3  (WT_ES2 + 8L * 2048L * 2048L)
#define WT_EOUT (WT_ES3 + 8L * 2048L * 2048L)
#define WT_TOTAL (WT_EOUT + 8L * 2048L * 512L)
__device__ bf16 g_wh[WT_TOTAL];
__device__ bf16 g_wl[WT_TOTAL];

// ---------------- helpers ----------------------------------------------------
__device__ __forceinline__ uint32_t smem_u32(const void* p) {
    return (uint32_t)__cvta_generic_to_shared(p);
}
__device__ __forceinline__ void cp16(uint32_t dst, const void* src) {
    asm volatile("cp.async.cg.shared.global [%0], [%1], 16;" :: "r"(dst), "l"(src));
}
__device__ __forceinline__ void cp_commit() {
    asm volatile("cp.async.commit_group;" ::: "memory");
}
__device__ __forceinline__ void cp_wait1() {
    asm volatile("cp.async.wait_group 1;" ::: "memory");
}
__device__ __forceinline__ void ldm_x4(uint32_t* r, uint32_t addr) {
    asm volatile("ldmatrix.sync.aligned.m8n8.x4.shared.b16 {%0,%1,%2,%3},[%4];"
                 : "=r"(r[0]), "=r"(r[1]), "=r"(r[2]), "=r"(r[3]) : "r"(addr));
}
__device__ __forceinline__ void mma16816(float* d, const uint32_t* a, const uint32_t* b) {
    asm volatile(
        "mma.sync.aligned.m16n8k16.row.col.f32.bf16.bf16.f32 "
        "{%0,%1,%2,%3},{%4,%5,%6,%7},{%8,%9},{%0,%1,%2,%3};"
        : "+f"(d[0]), "+f"(d[1]), "+f"(d[2]), "+f"(d[3])
        : "r"(a[0]), "r"(a[1]), "r"(a[2]), "r"(a[3]), "r"(b[0]), "r"(b[1]));
}
__device__ __forceinline__ void split1(float v, bf16& h, bf16& l) {
    h = __float2bfloat16(v);
    l = __float2bfloat16(v - __bfloat162float(h));
}

// ---------------- pipelined split-bf16 mma.sync GEMM -------------------------
// C[M,N] = (AH+AL)[M,K] @ (BH+BL)[N,K]^T + bias (3-term: hh + lh + hl)
template <bool GATHER, int OUTMODE, bool SILU>
__global__ void __launch_bounds__(256, 1)
mma2_gemm(const bf16* __restrict__ AH, const bf16* __restrict__ AL,
          const bf16* __restrict__ BH, const bf16* __restrict__ BL,
          const float* __restrict__ bias,
          bf16* __restrict__ OH, bf16* __restrict__ OL,
          float* __restrict__ OF,
          const bf16* __restrict__ XH, const bf16* __restrict__ XL,
          int K, int N,
          const int* __restrict__ mcnt, const int* __restrict__ gidx,
          float scale)
{
    const int M = mcnt ? *mcnt : NTOK;
    const int m0 = blockIdx.y * BM;
    if (m0 >= M) return;
    const int n0 = blockIdx.x * BN;

    extern __shared__ char sm[];
    const uint32_t sm0 = smem_u32(sm);

    const int tid  = threadIdx.x;
    const int lane = tid & 31;
    const int wid  = tid >> 5;
    const int wm   = wid >> 2;   // 0..1
    const int wn   = wid & 3;    // 0..3

    // ---- load slot setup ----
    const int lr = tid >> 2;     // 0..63
    const int lc = tid & 3;      // granule 0..3
    const char* aSrcH[2]; const char* aSrcL[2];
    uint32_t dA[2];
#pragma unroll
    for (int i = 0; i < 2; i++) {
        const int r = i * 64 + lr;
        long grow;
        if (GATHER) grow = (m0 + r < M) ? (long)gidx[m0 + r] : 0L;
        else        grow = m0 + r;
        aSrcH[i] = (const char*)(AH + grow * (long)K) + lc * 16;
        aSrcL[i] = (const char*)(AL + grow * (long)K) + lc * 16;
        dA[i] = (uint32_t)(r * ROWB + lc * 16);
    }
    const char* bSrcH[4]; const char* bSrcL[4];
    uint32_t dB[4];
#pragma unroll
    for (int i = 0; i < 4; i++) {
        const int r = i * 64 + lr;
        bSrcH[i] = (const char*)(BH + (long)(n0 + r) * K) + lc * 16;
        bSrcL[i] = (const char*)(BL + (long)(n0 + r) * K) + lc * 16;
        dB[i] = (uint32_t)(r * ROWB + lc * 16);
    }

    float acc[4][8][4];
#pragma unroll
    for (int mi = 0; mi < 4; mi++)
#pragma unroll
        for (int ni = 0; ni < 8; ni++)
#pragma unroll
            for (int q = 0; q < 4; q++) acc[mi][ni][q] = 0.f;

    auto load_stage = [&](int s, int kt) {
        const uint32_t su = sm0 + s * STG_BYTES;
        const long koff = (long)kt * 64;   // BK*2 bytes
#pragma unroll
        for (int i = 0; i < 2; i++) {
            cp16(su + dA[i], aSrcH[i] + koff);
            cp16(su + SA_BYTES + dA[i], aSrcL[i] + koff);
        }
#pragma unroll
        for (int i = 0; i < 4; i++) {
            cp16(su + 2 * SA_BYTES + dB[i], bSrcH[i] + koff);
            cp16(su + 2 * SA_BYTES + SB_BYTES + dB[i], bSrcL[i] + koff);
        }
    };

    const int niter = K / BK;   // >= 16 always
    load_stage(0, 0); cp_commit();
    load_stage(1, 1); cp_commit();

    const uint32_t aOff = (uint32_t)((wm * 64 + (lane & 15)) * ROWB + (lane >> 4) * 16);
    const uint32_t bOff = (uint32_t)(2 * SA_BYTES + (wn * 64 + (lane & 15)) * ROWB + (lane >> 4) * 16);

    for (int kt = 0; kt < niter; kt++) {
        cp_wait1();
        __syncthreads();
        if (kt + 2 < niter) load_stage((kt + 2) % STAGES, kt + 2);
        cp_commit();

        const uint32_t su = sm0 + (kt % STAGES) * STG_BYTES;
        const uint32_t aH = su + aOff;
        const uint32_t aL = aH + SA_BYTES;
        const uint32_t bHb = su + bOff;
        const uint32_t bLb = bHb + SB_BYTES;
#pragma unroll
        for (int k16 = 0; k16 < 2; k16++) {
            uint32_t ah[4][4], al[4][4], bh[8][2], bl[8][2];
#pragma unroll
            for (int mi = 0; mi < 4; mi++) {
                const uint32_t o = (uint32_t)(mi * 16 * ROWB + k16 * 32);
                ldm_x4(ah[mi], aH + o);
                ldm_x4(al[mi], aL + o);
            }
#pragma unroll
            for (int p = 0; p < 4; p++) {
                const uint32_t o = (uint32_t)(p * 16 * ROWB + k16 * 32);
                uint32_t r[4];
                ldm_x4(r, bHb + o);
                bh[2 * p][0] = r[0]; bh[2 * p][1] = r[2];
                bh[2 * p + 1][0] = r[1]; bh[2 * p + 1][1] = r[3];
                ldm_x4(r, bLb + o);
                bl[2 * p][0] = r[0]; bl[2 * p][1] = r[2];
                bl[2 * p + 1][0] = r[1]; bl[2 * p + 1][1] = r[3];
            }
#pragma unroll
            for (int mi = 0; mi < 4; mi++)
#pragma unroll
                for (int ni = 0; ni < 8; ni++) {
                    mma16816(acc[mi][ni], ah[mi], bh[ni]);
                    mma16816(acc[mi][ni], al[mi], bh[ni]);
                    mma16816(acc[mi][ni], ah[mi], bl[ni]);
                }
        }
        __syncthreads();
    }

    // ---- epilogue ----
    const int gid = lane >> 2;
    const int qid = lane & 3;
#pragma unroll
    for (int mi = 0; mi < 4; mi++) {
#pragma unroll
        for (int half = 0; half < 2; half++) {
            const int m = m0 + wm * 64 + mi * 16 + gid + half * 8;
            if (m >= M) continue;
            long orow;
            if (OUTMODE == OUT_SCAT) orow = (long)gidx[m] * N;
            else                     orow = (long)m * N;
#pragma unroll
            for (int ni = 0; ni < 8; ni++) {
                const int col = n0 + wn * 64 + ni * 8 + qid * 2;
                float v0 = acc[mi][ni][half * 2 + 0] + bias[col];
                float v1 = acc[mi][ni][half * 2 + 1] + bias[col + 1];
                if (SILU) {
                    const __nv_bfloat162 hh = *(const __nv_bfloat162*)(XH + (long)m * N + col);
                    const __nv_bfloat162 hl = *(const __nv_bfloat162*)(XL + (long)m * N + col);
                    const float a0 = __bfloat162float(hh.x) + __bfloat162float(hl.x);
                    const float a1 = __bfloat162float(hh.y) + __bfloat162float(hl.y);
                    v0 *= a0 / (1.f + __expf(-a0));
                    v1 *= a1 / (1.f + __expf(-a1));
                }
                if (OUTMODE == OUT_SPLIT) {
                    bf16 h0, l0, h1, l1;
                    split1(v0, h0, l0); split1(v1, h1, l1);
                    __nv_bfloat162 hv; hv.x = h0; hv.y = h1;
                    __nv_bfloat162 lv; lv.x = l0; lv.y = l1;
                    *(__nv_bfloat162*)(OH + orow + col) = hv;
                    *(__nv_bfloat162*)(OL + orow + col) = lv;
                } else if (OUTMODE == OUT_F32) {
                    OF[orow + col]     = v0;
                    OF[orow + col + 1] = v1;
                } else {
                    OF[orow + col]     += v0 * scale;
                    OF[orow + col + 1] += v1 * scale;
                }
            }
        }
    }
}

// ---------------- transpose+split: W[K,N] fp32 -> WTH/WTL[N,K] bf16 ----------
__global__ void __launch_bounds__(256)
transpose_split_kernel(const float* __restrict__ src, bf16* __restrict__ dh,
                       bf16* __restrict__ dl, int K, int N)
{
    __shared__ float s[32][33];
    const size_t bs = (size_t)K * N;
    src += blockIdx.z * bs;
    dh  += blockIdx.z * bs;
    dl  += blockIdx.z * bs;
    const int n0 = blockIdx.x * 32, k0 = blockIdx.y * 32;
    const int tx = threadIdx.x & 31, ty = threadIdx.x >> 5;
#pragma unroll
    for (int r = 0; r < 32; r += 8)
        s[ty + r][tx] = src[(size_t)(k0 + ty + r) * N + n0 + tx];
    __syncthreads();
#pragma unroll
    for (int r = 0; r < 32; r += 8) {
        const float v = s[tx][ty + r];
        bf16 h, l;
        split1(v, h, l);
        dh[(size_t)(n0 + ty + r) * K + k0 + tx] = h;
        dl[(size_t)(n0 + ty + r) * K + k0 + tx] = l;
    }
}

// ---------------- x split ----------------------------------------------------
__global__ void __launch_bounds__(256)
split_kernel(const float* __restrict__ src, bf16* __restrict__ dh,
             bf16* __restrict__ dl, long n)
{
    const long stride = (long)gridDim.x * blockDim.x;
    for (long i = (long)blockIdx.x * blockDim.x + threadIdx.x; i < n; i += stride) {
        bf16 h, l;
        split1(src[i], h, l);
        dh[i] = h; dl[i] = l;
    }
}

// ---------------- small kernels ----------------------------------------------
__global__ void __launch_bounds__(256)
logits_kernel(const float* __restrict__ rh, const float* __restrict__ W,
              const float* __restrict__ b, float* __restrict__ logits)
{
    const int t = blockIdx.x;
    const float* row = rh + (long)t * RHM;
    float p[EM];
#pragma unroll
    for (int e = 0; e < EM; e++) p[e] = 0.f;
    for (int k = threadIdx.x; k < RHM; k += 256) {
        const float v = row[k];
        const float* wr = W + (long)k * EM;
#pragma unroll
        for (int e = 0; e < EM; e++) p[e] = fmaf(v, wr[e], p[e]);
    }
#pragma unroll
    for (int e = 0; e < EM; e++)
#pragma unroll
        for (int off = 16; off > 0; off >>= 1)
            p[e] += __shfl_down_sync(0xffffffffu, p[e], off);
    __shared__ float red[EM][8];
    const int lane = threadIdx.x & 31, warp = threadIdx.x >> 5;
    if (lane == 0)
#pragma unroll
        for (int e = 0; e < EM; e++) red[e][warp] = p[e];
    __syncthreads();
    if (threadIdx.x < EM) {
        float s = b[threadIdx.x];
#pragma unroll
        for (int w = 0; w < 8; w++) s += red[threadIdx.x][w];
        logits[(long)t * EM + threadIdx.x] = s;
    }
}

__global__ void topk_kernel(const float* __restrict__ logits,
                            unsigned* __restrict__ maskb)
{
    const int t = blockIdx.x * blockDim.x + threadIdx.x;
    if (t >= NTOK) return;
    float v[EM];
#pragma unroll
    for (int e = 0; e < EM; e++) v[e] = logits[(long)t * EM + e];
    unsigned m = 0;
#pragma unroll
    for (int s = 0; s < TOPK; s++) {
        int best = 0;
        float bv = -INFINITY;
#pragma unroll
        for (int e = 0; e < EM; e++) {
            if (!((m >> e) & 1u) && v[e] > bv) { bv = v[e]; best = e; }
        }
        m |= 1u << best;
    }
    maskb[t] = m;
}

__global__ void __launch_bounds__(256)
compact_kernel(const unsigned* __restrict__ maskb,
               int* __restrict__ idx, int* __restrict__ cnt)
{
    const int e = blockIdx.x;
    __shared__ int s_base;
    __shared__ int s_warp[8];
    if (threadIdx.x == 0) s_base = 0;
    __syncthreads();
    const int lane = threadIdx.x & 31, warp = threadIdx.x >> 5;
    for (int c = 0; c < NTOK; c += 256) {
        const int t = c + threadIdx.x;
        const int p = (maskb[t] >> e) & 1u;
        const unsigned bal = __ballot_sync(0xffffffffu, p);
        if (lane == 0) s_warp[warp] = __popc(bal);
        __syncthreads();
        int woff = 0, tot = 0;
        for (int w = 0; w < 8; w++) { if (w < warp) woff += s_warp[w]; tot += s_warp[w]; }
        const int rank = __popc(bal & ((1u << lane) - 1u));
        if (p) idx[e * NTOK + s_base + woff + rank] = t;
        __syncthreads();
        if (threadIdx.x == 0) s_base += tot;
        __syncthreads();
    }
    if (threadIdx.x == 0) cnt[e] = s_base;
}

__global__ void zero_kernel(float* __restrict__ out, long n)
{
    const long stride = (long)gridDim.x * blockDim.x;
    for (long i = (long)blockIdx.x * blockDim.x + threadIdx.x; i < n; i += stride)
        out[i] = 0.f;
}

// ---------------- launcher ---------------------------------------------------
extern "C" void kernel_launch(void* const* d_in, const int* in_sizes, int n_in,
                              void* d_out, int out_size)
{
    const float* x       = (const float*)d_in[0];
    const float* r_in_w  = (const float*)d_in[1];
    const float* r_in_b  = (const float*)d_in[2];
    const float* rs_w1   = (const float*)d_in[3];
    const float* rs_b1   = (const float*)d_in[4];
    const float* rs_w2   = (const float*)d_in[5];
    const float* rs_b2   = (const float*)d_in[6];
    const float* rs_w3   = (const float*)d_in[7];
    const float* rs_b3   = (const float*)d_in[8];
    const float* r_out_w = (const float*)d_in[9];
    const float* r_out_b = (const float*)d_in[10];
    const float* e_in_b  = (const float*)d_in[12];
    const float* es_b1   = (const float*)d_in[14];
    const float* es_b2   = (const float*)d_in[16];
    const float* es_b3   = (const float*)d_in[18];
    const float* e_out_b = (const float*)d_in[20];
    const float* e_in_w  = (const float*)d_in[11];
    const float* es_w1   = (const float*)d_in[13];
    const float* es_w2   = (const float*)d_in[15];
    const float* es_w3   = (const float*)d_in[17];
    const float* e_out_w = (const float*)d_in[19];
    float* out = (float*)d_out;

    bf16 *xh, *xl, *b1h, *b1l, *b2h, *b2l, *b3h, *b3l, *wh, *wl;
    float *f32buf, *logits;
    unsigned* maskb;
    int *idx, *cnt;
    cudaGetSymbolAddress((void**)&xh, g_xh);   cudaGetSymbolAddress((void**)&xl, g_xl);
    cudaGetSymbolAddress((void**)&b1h, g_b1h); cudaGetSymbolAddress((void**)&b1l, g_b1l);
    cudaGetSymbolAddress((void**)&b2h, g_b2h); cudaGetSymbolAddress((void**)&b2l, g_b2l);
    cudaGetSymbolAddress((void**)&b3h, g_b3h); cudaGetSymbolAddress((void**)&b3l, g_b3l);
    cudaGetSymbolAddress((void**)&f32buf, g_f32);
    cudaGetSymbolAddress((void**)&logits, g_logits);
    cudaGetSymbolAddress((void**)&maskb, g_maskb);
    cudaGetSymbolAddress((void**)&idx, g_idx);
    cudaGetSymbolAddress((void**)&cnt, g_cnt);
    cudaGetSymbolAddress((void**)&wh, g_wh);
    cudaGetSymbolAddress((void**)&wl, g_wl);

    cudaFuncSetAttribute(mma2_gemm<false, OUT_SPLIT, false>,
                         cudaFuncAttributeMaxDynamicSharedMemorySize, SMEM_DYN);
    cudaFuncSetAttribute(mma2_gemm<false, OUT_SPLIT, true>,
                         cudaFuncAttributeMaxDynamicSharedMemorySize, SMEM_DYN);
    cudaFuncSetAttribute(mma2_gemm<false, OUT_F32, false>,
                         cudaFuncAttributeMaxDynamicSharedMemorySize, SMEM_DYN);
    cudaFuncSetAttribute(mma2_gemm<true, OUT_SPLIT, false>,
                         cudaFuncAttributeMaxDynamicSharedMemorySize, SMEM_DYN);
    cudaFuncSetAttribute(mma2_gemm<false, OUT_SCAT, false>,
                         cudaFuncAttributeMaxDynamicSharedMemorySize, SMEM_DYN);

    const dim3 tb(256);
    // launches 0..4 (so launch #5 = first big GEMM for ncu -s 5)
    split_kernel<<<1024, tb>>>(x, xh, xl, (long)NTOK * DM);
    transpose_split_kernel<<<dim3(1024 / 32, 512 / 32, 1), tb>>>(r_in_w, wh + WT_RIN, wl + WT_RIN, 512, 1024);
    transpose_split_kernel<<<dim3(1024 / 32, 1024 / 32, 1), tb>>>(rs_w1, wh + WT_RS1, wl + WT_RS1, 1024, 1024);
    transpose_split_kernel<<<dim3(1024 / 32, 1024 / 32, 1), tb>>>(rs_w2, wh + WT_RS2, wl + WT_RS2, 1024, 1024);
    transpose_split_kernel<<<dim3(1024 / 32, 1024 / 32, 1), tb>>>(rs_w3, wh + WT_RS3, wl + WT_RS3, 1024, 1024);

    const dim3 gR(RHM / BN, NTOK / BM);   // 4 x 128
    const dim3 gH(HM / BN, NTOK / BM);    // 8 x 128
    const dim3 gO(DM / BN, NTOK / BM);    // 2 x 128

    // launch #5: router GEMM1 (profiled by ncu -s 5 -c 1)
    mma2_gemm<false, OUT_SPLIT, false><<<gR, tb, SMEM_DYN>>>(
        xh, xl, wh + WT_RIN, wl + WT_RIN, r_in_b, b1h, b1l, nullptr,
        nullptr, nullptr, DM, RHM, nullptr, nullptr, 1.f);

    // remaining weight transposes
    transpose_split_kernel<<<dim3(2048 / 32, 512 / 32, EM), tb>>>(e_in_w, wh + WT_EIN, wl + WT_EIN, 512, 2048);
    transpose_split_kernel<<<dim3(2048 / 32, 2048 / 32, EM), tb>>>(es_w1, wh + WT_ES1, wl + WT_ES1, 2048, 2048);
    transpose_split_kernel<<<dim3(2048 / 32, 2048 / 32, EM), tb>>>(es_w2, wh + WT_ES2, wl + WT_ES2, 2048, 2048);
    transpose_split_kernel<<<dim3(2048 / 32, 2048 / 32, EM), tb>>>(es_w3, wh + WT_ES3, wl + WT_ES3, 2048, 2048);
    transpose_split_kernel<<<dim3(512 / 32, 2048 / 32, EM), tb>>>(e_out_w, wh + WT_EOUT, wl + WT_EOUT, 2048, 512);

    // ---- rest of router ----
    mma2_gemm<false, OUT_SPLIT, false><<<gR, tb, SMEM_DYN>>>(
        b1h, b1l, wh + WT_RS1, wl + WT_RS1, rs_b1, b2h, b2l, nullptr,
        nullptr, nullptr, RHM, RHM, nullptr, nullptr, 1.f);
    mma2_gemm<false, OUT_SPLIT, true><<<gR, tb, SMEM_DYN>>>(
        b1h, b1l, wh + WT_RS2, wl + WT_RS2, rs_b2, b3h, b3l, nullptr,
        b2h, b2l, RHM, RHM, nullptr, nullptr, 1.f);
    mma2_gemm<false, OUT_F32, false><<<gR, tb, SMEM_DYN>>>(
        b3h, b3l, wh + WT_RS3, wl + WT_RS3, rs_b3, nullptr, nullptr, f32buf,
        nullptr, nullptr, RHM, RHM, nullptr, nullptr, 1.f);
    logits_kernel<<<NTOK, tb>>>(f32buf, r_out_w, r_out_b, logits);
    topk_kernel<<<NTOK / 256, tb>>>(logits, maskb);
    compact_kernel<<<EM, tb>>>(maskb, idx, cnt);
    zero_kernel<<<1024, tb>>>(out, (long)NTOK * DM);

    // ---- experts (selected tokens only) ----
    for (int e = 0; e < EM; e++) {
        const int* ce = cnt + e;
        const int* ie = idx + e * NTOK;
        mma2_gemm<true, OUT_SPLIT, false><<<gH, tb, SMEM_DYN>>>(
            xh, xl, wh + WT_EIN + (long)e * DM * HM, wl + WT_EIN + (long)e * DM * HM,
            e_in_b + (long)e * HM, b1h, b1l, nullptr,
            nullptr, nullptr, DM, HM, ce, ie, 1.f);
        mma2_gemm<false, OUT_SPLIT, false><<<gH, tb, SMEM_DYN>>>(
            b1h, b1l, wh + WT_ES1 + (long)e * HM * HM, wl + WT_ES1 + (long)e * HM * HM,
            es_b1 + (long)e * HM, b2h, b2l, nullptr,
            nullptr, nullptr, HM, HM, ce, nullptr, 1.f);
        mma2_gemm<false, OUT_SPLIT, true><<<gH, tb, SMEM_DYN>>>(
            b1h, b1l, wh + WT_ES2 + (long)e * HM * HM, wl + WT_ES2 + (long)e * HM * HM,
            es_b2 + (long)e * HM, b3h, b3l, nullptr,
            b2h, b2l, HM, HM, ce, nullptr, 1.f);
        mma2_gemm<false, OUT_SPLIT, false><<<gH, tb, SMEM_DYN>>>(
            b3h, b3l, wh + WT_ES3 + (long)e * HM * HM, wl + WT_ES3 + (long)e * HM * HM,
            es_b3 + (long)e * HM, b2h, b2l, nullptr,
            nullptr, nullptr, HM, HM, ce, nullptr, 1.f);
        mma2_gemm<false, OUT_SCAT, false><<<gO, tb, SMEM_DYN>>>(
            b2h, b2l, wh + WT_EOUT + (long)e * HM * DM, wl + WT_EOUT + (long)e * HM * DM,
            e_out_b + (long)e * DM, nullptr, nullptr, out,
            nullptr, nullptr, HM, DM, ce, ie, 1.f / EM);
    }
}

// round 5
// speedup vs baseline: 1.7753x; 1.7753x over previous
#include <cuda_runtime.h>
#include <cuda_bf16.h>
#include <math.h>
#include <stdint.h>

// Problem constants
#define NTOK 16384
#define DM   512
#define RHM  1024
#define HM   2048
#define EM   8
#define TOPK 4

// GEMM tile config
#define BM 128
#define BN 128
#define BK 32
#define STAGES 4
#define AROWB 80                        // 64B data + 16B pad
#define BROWB 272                       // 256B data + 16B pad
#define SA_BYTES (128 * AROWB)          // 10240
#define SB_BYTES (32 * BROWB)           // 8704
#define STG_BYTES (2 * SA_BYTES + 2 * SB_BYTES)   // 37888
#define SMEM_DYN (STAGES * STG_BYTES)   // 151552

#define OUT_SPLIT 0
#define OUT_F32   1
#define OUT_SCAT  2

typedef __nv_bfloat16 bf16;

// ---------------- scratch --------------------------------------------------
__device__ bf16  g_xh[(size_t)NTOK * DM];
__device__ bf16  g_xl[(size_t)NTOK * DM];
__device__ bf16  g_b1h[(size_t)NTOK * HM];
__device__ bf16  g_b1l[(size_t)NTOK * HM];
__device__ bf16  g_b2h[(size_t)NTOK * HM];
__device__ bf16  g_b2l[(size_t)NTOK * HM];
__device__ bf16  g_b3h[(size_t)NTOK * HM];
__device__ bf16  g_b3l[(size_t)NTOK * HM];
__device__ float g_f32[(size_t)NTOK * RHM];
__device__ float g_logits[(size_t)NTOK * EM];
__device__ unsigned g_maskb[NTOK];
__device__ int   g_idx[EM * NTOK];
__device__ int   g_cnt[EM];
// bf16 hi/lo weight copies in NATIVE [K,N] layout
#define WT_RIN  0L
#define WT_RS1  (WT_RIN + 512L * 1024L)
#define WT_RS2  (WT_RS1 + 1024L * 1024L)
#define WT_RS3  (WT_RS2 + 1024L * 1024L)
#define WT_EIN  (WT_RS3 + 1024L * 1024L)
#define WT_ES1  (WT_EIN + 8L * 512L * 2048L)
#define WT_ES2  (WT_ES1 + 8L * 2048L * 2048L)
#define WT_ES3  (WT_ES2 + 8L * 2048L * 2048L)
#define WT_EOUT (WT_ES3 + 8L * 2048L * 2048L)
#define WT_TOTAL (WT_EOUT + 8L * 2048L * 512L)
__device__ bf16 g_wh[WT_TOTAL];
__device__ bf16 g_wl[WT_TOTAL];

// ---------------- helpers --------------------------------------------------
__device__ __forceinline__ uint32_t smem_u32(const void* p) {
    return (uint32_t)__cvta_generic_to_shared(p);
}
__device__ __forceinline__ void cp16(uint32_t dst, const void* src) {
    asm volatile("cp.async.cg.shared.global [%0], [%1], 16;" :: "r"(dst), "l"(src));
}
__device__ __forceinline__ void cp_commit() {
    asm volatile("cp.async.commit_group;" ::: "memory");
}
__device__ __forceinline__ void cp_wait2() {
    asm volatile("cp.async.wait_group 2;" ::: "memory");
}
__device__ __forceinline__ void ldm_x4(uint32_t* r, uint32_t addr) {
    asm volatile("ldmatrix.sync.aligned.m8n8.x4.shared.b16 {%0,%1,%2,%3},[%4];"
                 : "=r"(r[0]), "=r"(r[1]), "=r"(r[2]), "=r"(r[3]) : "r"(addr));
}
__device__ __forceinline__ void ldm_x4t(uint32_t* r, uint32_t addr) {
    asm volatile("ldmatrix.sync.aligned.m8n8.x4.trans.shared.b16 {%0,%1,%2,%3},[%4];"
                 : "=r"(r[0]), "=r"(r[1]), "=r"(r[2]), "=r"(r[3]) : "r"(addr));
}
__device__ __forceinline__ void mma16816(float* d, const uint32_t* a, const uint32_t* b) {
    asm volatile(
        "mma.sync.aligned.m16n8k16.row.col.f32.bf16.bf16.f32 "
        "{%0,%1,%2,%3},{%4,%5,%6,%7},{%8,%9},{%0,%1,%2,%3};"
        : "+f"(d[0]), "+f"(d[1]), "+f"(d[2]), "+f"(d[3])
        : "r"(a[0]), "r"(a[1]), "r"(a[2]), "r"(a[3]), "r"(b[0]), "r"(b[1]));
}
__device__ __forceinline__ void split1(float v, bf16& h, bf16& l) {
    h = __float2bfloat16(v);
    l = __float2bfloat16(v - __bfloat162float(h));
}

// ---------------- pipelined split-bf16 mma.sync GEMM -----------------------
// C[M,N] = (AH+AL)[M,K] @ (BH+BL)[K,N] + bias   (3-term: hh + lh + hl)
// A K-major, B row-major [K,N] (trans-ldmatrix). 256 thr, warp tile 64x32.
template <bool GATHER, int OUTMODE, bool SILU>
__global__ void __launch_bounds__(256, 1)
mma2_gemm(const bf16* __restrict__ AH, const bf16* __restrict__ AL,
          const bf16* __restrict__ BH, const bf16* __restrict__ BL,
          const float* __restrict__ bias,
          bf16* __restrict__ OH, bf16* __restrict__ OL,
          float* __restrict__ OF,
          const bf16* __restrict__ XH, const bf16* __restrict__ XL,
          int K, int N,
          const int* __restrict__ mcnt, const int* __restrict__ gidx,
          float scale)
{
    const int M = mcnt ? *mcnt : NTOK;
    const int m0 = blockIdx.y * BM;
    if (m0 >= M) return;
    const int n0 = blockIdx.x * BN;

    extern __shared__ char sm[];
    const uint32_t sm0 = smem_u32(sm);

    const int tid  = threadIdx.x;
    const int lane = tid & 31;
    const int wid  = tid >> 5;
    const int wm   = wid >> 2;   // 0..1  (64-row slab)
    const int wn   = wid & 3;    // 0..3  (32-col slab)

    // ---- load slots: A 2/thread, B 2/thread (x hi/lo) ----
    const char* aSrcH[2]; const char* aSrcL[2];
    uint32_t dA[2];
#pragma unroll
    for (int i = 0; i < 2; i++) {
        const int idx = i * 256 + tid;
        const int r = idx >> 2;          // 0..127
        const int g = idx & 3;           // 16B granule in 64B row
        long grow;
        if (GATHER) grow = (m0 + r < M) ? (long)gidx[m0 + r] : 0L;
        else        grow = m0 + r;
        aSrcH[i] = (const char*)(AH + grow * (long)K) + g * 16;
        aSrcL[i] = (const char*)(AL + grow * (long)K) + g * 16;
        dA[i] = (uint32_t)(r * AROWB + g * 16);
    }
    const char* bSrcH[2]; const char* bSrcL[2];
    uint32_t dB[2];
#pragma unroll
    for (int i = 0; i < 2; i++) {
        const int idx = i * 256 + tid;
        const int r = idx >> 4;          // 0..31 (k row)
        const int g = idx & 15;          // 16B granule in 256B row
        bSrcH[i] = (const char*)(BH + (long)r * N + n0) + g * 16;
        bSrcL[i] = (const char*)(BL + (long)r * N + n0) + g * 16;
        dB[i] = (uint32_t)(r * BROWB + g * 16);
    }

    float acc[4][4][4];
#pragma unroll
    for (int mi = 0; mi < 4; mi++)
#pragma unroll
        for (int ni = 0; ni < 4; ni++)
#pragma unroll
            for (int q = 0; q < 4; q++) acc[mi][ni][q] = 0.f;

    auto load_stage = [&](int s, int kt) {
        const uint32_t su = sm0 + s * STG_BYTES;
        const long kA = (long)kt * 64;          // BK bf16 = 64B along K-major A
        const long kB = (long)kt * BK * N * 2;  // BK rows of B
#pragma unroll
        for (int i = 0; i < 2; i++) {
            cp16(su + dA[i], aSrcH[i] + kA);
            cp16(su + SA_BYTES + dA[i], aSrcL[i] + kA);
        }
#pragma unroll
        for (int i = 0; i < 2; i++) {
            cp16(su + 2 * SA_BYTES + dB[i], bSrcH[i] + kB);
            cp16(su + 2 * SA_BYTES + SB_BYTES + dB[i], bSrcL[i] + kB);
        }
    };

    const int niter = K / BK;   // >= 16
    load_stage(0, 0); cp_commit();
    load_stage(1, 1); cp_commit();
    load_stage(2, 2); cp_commit();

    const uint32_t aOff = (uint32_t)((wm * 64 + (lane & 15)) * AROWB + (lane >> 4) * 16);
    const uint32_t bOff = (uint32_t)(2 * SA_BYTES + (lane & 15) * BROWB
                                     + (wn * 32 + (lane >> 4) * 8) * 2);

    for (int kt = 0; kt < niter; kt++) {
        cp_wait2();
        __syncthreads();
        if (kt + 3 < niter) load_stage((kt + 3) & 3, kt + 3);
        cp_commit();

        const uint32_t su = sm0 + (kt & 3) * STG_BYTES;
        const uint32_t aH = su + aOff;
        const uint32_t aL = aH + SA_BYTES;
        const uint32_t bHb = su + bOff;
        const uint32_t bLb = bHb + SB_BYTES;
#pragma unroll
        for (int k16 = 0; k16 < 2; k16++) {
            uint32_t ah[4][4], al[4][4], bh[4][2], bl[4][2];
#pragma unroll
            for (int mi = 0; mi < 4; mi++) {
                const uint32_t o = (uint32_t)(mi * 16 * AROWB + k16 * 32);
                ldm_x4(ah[mi], aH + o);
                ldm_x4(al[mi], aL + o);
            }
#pragma unroll
            for (int p = 0; p < 2; p++) {
                const uint32_t o = (uint32_t)(k16 * 16 * BROWB + p * 32);
                uint32_t r[4];
                ldm_x4t(r, bHb + o);
                bh[2 * p][0] = r[0]; bh[2 * p][1] = r[1];
                bh[2 * p + 1][0] = r[2]; bh[2 * p + 1][1] = r[3];
                ldm_x4t(r, bLb + o);
                bl[2 * p][0] = r[0]; bl[2 * p][1] = r[1];
                bl[2 * p + 1][0] = r[2]; bl[2 * p + 1][1] = r[3];
            }
#pragma unroll
            for (int mi = 0; mi < 4; mi++)
#pragma unroll
                for (int ni = 0; ni < 4; ni++) {
                    mma16816(acc[mi][ni], ah[mi], bh[ni]);
                    mma16816(acc[mi][ni], al[mi], bh[ni]);
                    mma16816(acc[mi][ni], ah[mi], bl[ni]);
                }
        }
        __syncthreads();
    }

    // ---- epilogue ----
    const int gid = lane >> 2;
    const int qid = lane & 3;
#pragma unroll
    for (int mi = 0; mi < 4; mi++) {
#pragma unroll
        for (int half = 0; half < 2; half++) {
            const int m = m0 + wm * 64 + mi * 16 + gid + half * 8;
            if (m >= M) continue;
            long orow;
            if (OUTMODE == OUT_SCAT) orow = (long)gidx[m] * N;
            else                     orow = (long)m * N;
#pragma unroll
            for (int ni = 0; ni < 4; ni++) {
                const int col = n0 + wn * 32 + ni * 8 + qid * 2;
                float v0 = acc[mi][ni][half * 2 + 0] + bias[col];
                float v1 = acc[mi][ni][half * 2 + 1] + bias[col + 1];
                if (SILU) {
                    const __nv_bfloat162 hh = *(const __nv_bfloat162*)(XH + (long)m * N + col);
                    const __nv_bfloat162 hl = *(const __nv_bfloat162*)(XL + (long)m * N + col);
                    const float a0 = __bfloat162float(hh.x) + __bfloat162float(hl.x);
                    const float a1 = __bfloat162float(hh.y) + __bfloat162float(hl.y);
                    v0 *= a0 / (1.f + __expf(-a0));
                    v1 *= a1 / (1.f + __expf(-a1));
                }
                if (OUTMODE == OUT_SPLIT) {
                    bf16 h0, l0, h1, l1;
                    split1(v0, h0, l0); split1(v1, h1, l1);
                    __nv_bfloat162 hv; hv.x = h0; hv.y = h1;
                    __nv_bfloat162 lv; lv.x = l0; lv.y = l1;
                    *(__nv_bfloat162*)(OH + orow + col) = hv;
                    *(__nv_bfloat162*)(OL + orow + col) = lv;
                } else if (OUTMODE == OUT_F32) {
                    OF[orow + col]     = v0;
                    OF[orow + col + 1] = v1;
                } else {
                    OF[orow + col]     += v0 * scale;
                    OF[orow + col + 1] += v1 * scale;
                }
            }
        }
    }
}

// ---------------- fp32 -> bf16 hi/lo elementwise split ----------------------
__global__ void __launch_bounds__(256)
split_kernel(const float* __restrict__ src, bf16* __restrict__ dh,
             bf16* __restrict__ dl, long n)
{
    const long stride = (long)gridDim.x * blockDim.x * 4;
    for (long i0 = ((long)blockIdx.x * blockDim.x + threadIdx.x) * 4; i0 < n; i0 += stride) {
        const float4 v = *(const float4*)(src + i0);
        bf16 h0, l0, h1, l1, h2, l2, h3, l3;
        split1(v.x, h0, l0); split1(v.y, h1, l1);
        split1(v.z, h2, l2); split1(v.w, h3, l3);
        __nv_bfloat162 ha, hb, la, lb;
        ha.x = h0; ha.y = h1; hb.x = h2; hb.y = h3;
        la.x = l0; la.y = l1; lb.x = l2; lb.y = l3;
        *(__nv_bfloat162*)(dh + i0)     = ha;
        *(__nv_bfloat162*)(dh + i0 + 2) = hb;
        *(__nv_bfloat162*)(dl + i0)     = la;
        *(__nv_bfloat162*)(dl + i0 + 2) = lb;
    }
}

// ---------------- small kernels ---------------------------------------------
__global__ void __launch_bounds__(256)
logits_kernel(const float* __restrict__ rh, const float* __restrict__ W,
              const float* __restrict__ b, float* __restrict__ logits)
{
    const int t = blockIdx.x;
    const float* row = rh + (long)t * RHM;
    float p[EM];
#pragma unroll
    for (int e = 0; e < EM; e++) p[e] = 0.f;
    for (int k = threadIdx.x; k < RHM; k += 256) {
        const float v = row[k];
        const float* wr = W + (long)k * EM;
#pragma unroll
        for (int e = 0; e < EM; e++) p[e] = fmaf(v, wr[e], p[e]);
    }
#pragma unroll
    for (int e = 0; e < EM; e++)
#pragma unroll
        for (int off = 16; off > 0; off >>= 1)
            p[e] += __shfl_down_sync(0xffffffffu, p[e], off);
    __shared__ float red[EM][8];
    const int lane = threadIdx.x & 31, warp = threadIdx.x >> 5;
    if (lane == 0)
#pragma unroll
        for (int e = 0; e < EM; e++) red[e][warp] = p[e];
    __syncthreads();
    if (threadIdx.x < EM) {
        float s = b[threadIdx.x];
#pragma unroll
        for (int w = 0; w < 8; w++) s += red[threadIdx.x][w];
        logits[(long)t * EM + threadIdx.x] = s;
    }
}

__global__ void topk_kernel(const float* __restrict__ logits,
                            unsigned* __restrict__ maskb)
{
    const int t = blockIdx.x * blockDim.x + threadIdx.x;
    if (t >= NTOK) return;
    float v[EM];
#pragma unroll
    for (int e = 0; e < EM; e++) v[e] = logits[(long)t * EM + e];
    unsigned m = 0;
#pragma unroll
    for (int s = 0; s < TOPK; s++) {
        int best = 0;
        float bv = -INFINITY;
#pragma unroll
        for (int e = 0; e < EM; e++) {
            if (!((m >> e) & 1u) && v[e] > bv) { bv = v[e]; best = e; }
        }
        m |= 1u << best;
    }
    maskb[t] = m;
}

__global__ void __launch_bounds__(256)
compact_kernel(const unsigned* __restrict__ maskb,
               int* __restrict__ idx, int* __restrict__ cnt)
{
    const int e = blockIdx.x;
    __shared__ int s_base;
    __shared__ int s_warp[8];
    if (threadIdx.x == 0) s_base = 0;
    __syncthreads();
    const int lane = threadIdx.x & 31, warp = threadIdx.x >> 5;
    for (int c = 0; c < NTOK; c += 256) {
        const int t = c + threadIdx.x;
        const int p = (maskb[t] >> e) & 1u;
        const unsigned bal = __ballot_sync(0xffffffffu, p);
        if (lane == 0) s_warp[warp] = __popc(bal);
        __syncthreads();
        int woff = 0, tot = 0;
        for (int w = 0; w < 8; w++) { if (w < warp) woff += s_warp[w]; tot += s_warp[w]; }
        const int rank = __popc(bal & ((1u << lane) - 1u));
        if (p) idx[e * NTOK + s_base + woff + rank] = t;
        __syncthreads();
        if (threadIdx.x == 0) s_base += tot;
        __syncthreads();
    }
    if (threadIdx.x == 0) cnt[e] = s_base;
}

__global__ void zero_kernel(float* __restrict__ out, long n)
{
    const long stride = (long)gridDim.x * blockDim.x;
    for (long i = (long)blockIdx.x * blockDim.x + threadIdx.x; i < n; i += stride)
        out[i] = 0.f;
}

// ---------------- launcher ---------------------------------------------------
extern "C" void kernel_launch(void* const* d_in, const int* in_sizes, int n_in,
                              void* d_out, int out_size)
{
    const float* x       = (const float*)d_in[0];
    const float* r_in_w  = (const float*)d_in[1];
    const float* r_in_b  = (const float*)d_in[2];
    const float* rs_w1   = (const float*)d_in[3];
    const float* rs_b1   = (const float*)d_in[4];
    const float* rs_w2   = (const float*)d_in[5];
    const float* rs_b2   = (const float*)d_in[6];
    const float* rs_w3   = (const float*)d_in[7];
    const float* rs_b3   = (const float*)d_in[8];
    const float* r_out_w = (const float*)d_in[9];
    const float* r_out_b = (const float*)d_in[10];
    const float* e_in_w  = (const float*)d_in[11];
    const float* e_in_b  = (const float*)d_in[12];
    const float* es_w1   = (const float*)d_in[13];
    const float* es_b1   = (const float*)d_in[14];
    const float* es_w2   = (const float*)d_in[15];
    const float* es_b2   = (const float*)d_in[16];
    const float* es_w3   = (const float*)d_in[17];
    const float* es_b3   = (const float*)d_in[18];
    const float* e_out_w = (const float*)d_in[19];
    const float* e_out_b = (const float*)d_in[20];
    float* out = (float*)d_out;

    bf16 *xh, *xl, *b1h, *b1l, *b2h, *b2l, *b3h, *b3l, *wh, *wl;
    float *f32buf, *logits;
    unsigned* maskb;
    int *idx, *cnt;
    cudaGetSymbolAddress((void**)&xh, g_xh);   cudaGetSymbolAddress((void**)&xl, g_xl);
    cudaGetSymbolAddress((void**)&b1h, g_b1h); cudaGetSymbolAddress((void**)&b1l, g_b1l);
    cudaGetSymbolAddress((void**)&b2h, g_b2h); cudaGetSymbolAddress((void**)&b2l, g_b2l);
    cudaGetSymbolAddress((void**)&b3h, g_b3h); cudaGetSymbolAddress((void**)&b3l, g_b3l);
    cudaGetSymbolAddress((void**)&f32buf, g_f32);
    cudaGetSymbolAddress((void**)&logits, g_logits);
    cudaGetSymbolAddress((void**)&maskb, g_maskb);
    cudaGetSymbolAddress((void**)&idx, g_idx);
    cudaGetSymbolAddress((void**)&cnt, g_cnt);
    cudaGetSymbolAddress((void**)&wh, g_wh);
    cudaGetSymbolAddress((void**)&wl, g_wl);

    cudaFuncSetAttribute(mma2_gemm<false, OUT_SPLIT, false>,
                         cudaFuncAttributeMaxDynamicSharedMemorySize, SMEM_DYN);
    cudaFuncSetAttribute(mma2_gemm<false, OUT_SPLIT, true>,
                         cudaFuncAttributeMaxDynamicSharedMemorySize, SMEM_DYN);
    cudaFuncSetAttribute(mma2_gemm<false, OUT_F32, false>,
                         cudaFuncAttributeMaxDynamicSharedMemorySize, SMEM_DYN);
    cudaFuncSetAttribute(mma2_gemm<true, OUT_SPLIT, false>,
                         cudaFuncAttributeMaxDynamicSharedMemorySize, SMEM_DYN);
    cudaFuncSetAttribute(mma2_gemm<false, OUT_SCAT, false>,
                         cudaFuncAttributeMaxDynamicSharedMemorySize, SMEM_DYN);

    const dim3 tb(256);
    const dim3 gR(RHM / BN, NTOK / BM);   // 8 x 128
    const dim3 gH(HM / BN, NTOK / BM);    // 16 x 128
    const dim3 gO(DM / BN, NTOK / BM);    // 4 x 128

    // interleave splits with GEMMs so early launch indices include GEMMs
    split_kernel<<<512, tb>>>(x, xh, xl, (long)NTOK * DM);
    split_kernel<<<512, tb>>>(r_in_w, wh + WT_RIN, wl + WT_RIN, 512L * 1024L);
    mma2_gemm<false, OUT_SPLIT, false><<<gR, tb, SMEM_DYN>>>(
        xh, xl, wh + WT_RIN, wl + WT_RIN, r_in_b, b1h, b1l, nullptr,
        nullptr, nullptr, DM, RHM, nullptr, nullptr, 1.f);
    split_kernel<<<512, tb>>>(rs_w1, wh + WT_RS1, wl + WT_RS1, 1024L * 1024L);
    mma2_gemm<false, OUT_SPLIT, false><<<gR, tb, SMEM_DYN>>>(
        b1h, b1l, wh + WT_RS1, wl + WT_RS1, rs_b1, b2h, b2l, nullptr,
        nullptr, nullptr, RHM, RHM, nullptr, nullptr, 1.f);
    split_kernel<<<512, tb>>>(rs_w2, wh + WT_RS2, wl + WT_RS2, 1024L * 1024L);
    mma2_gemm<false, OUT_SPLIT, true><<<gR, tb, SMEM_DYN>>>(
        b1h, b1l, wh + WT_RS2, wl + WT_RS2, rs_b2, b3h, b3l, nullptr,
        b2h, b2l, RHM, RHM, nullptr, nullptr, 1.f);
    split_kernel<<<512, tb>>>(rs_w3, wh + WT_RS3, wl + WT_RS3, 1024L * 1024L);
    mma2_gemm<false, OUT_F32, false><<<gR, tb, SMEM_DYN>>>(
        b3h, b3l, wh + WT_RS3, wl + WT_RS3, rs_b3, nullptr, nullptr, f32buf,
        nullptr, nullptr, RHM, RHM, nullptr, nullptr, 1.f);
    logits_kernel<<<NTOK, tb>>>(f32buf, r_out_w, r_out_b, logits);
    topk_kernel<<<NTOK / 256, tb>>>(logits, maskb);
    compact_kernel<<<EM, tb>>>(maskb, idx, cnt);
    zero_kernel<<<1024, tb>>>(out, (long)NTOK * DM);

    // expert weight splits
    split_kernel<<<2048, tb>>>(e_in_w, wh + WT_EIN, wl + WT_EIN, 8L * 512L * 2048L);
    split_kernel<<<4096, tb>>>(es_w1, wh + WT_ES1, wl + WT_ES1, 8L * 2048L * 2048L);
    split_kernel<<<4096, tb>>>(es_w2, wh + WT_ES2, wl + WT_ES2, 8L * 2048L * 2048L);
    split_kernel<<<4096, tb>>>(es_w3, wh + WT_ES3, wl + WT_ES3, 8L * 2048L * 2048L);
    split_kernel<<<2048, tb>>>(e_out_w, wh + WT_EOUT, wl + WT_EOUT, 8L * 2048L * 512L);

    // ---- experts (selected tokens only) ----
    for (int e = 0; e < EM; e++) {
        const int* ce = cnt + e;
        const int* ie = idx + e * NTOK;
        mma2_gemm<true, OUT_SPLIT, false><<<gH, tb, SMEM_DYN>>>(
            xh, xl, wh + WT_EIN + (long)e * DM * HM, wl + WT_EIN + (long)e * DM * HM,
            e_in_b + (long)e * HM, b1h, b1l, nullptr,
            nullptr, nullptr, DM, HM, ce, ie, 1.f);
        mma2_gemm<false, OUT_SPLIT, false><<<gH, tb, SMEM_DYN>>>(
            b1h, b1l, wh + WT_ES1 + (long)e * HM * HM, wl + WT_ES1 + (long)e * HM * HM,
            es_b1 + (long)e * HM, b2h, b2l, nullptr,
            nullptr, nullptr, HM, HM, ce, nullptr, 1.f);
        mma2_gemm<false, OUT_SPLIT, true><<<gH, tb, SMEM_DYN>>>(
            b1h, b1l, wh + WT_ES2 + (long)e * HM * HM, wl + WT_ES2 + (long)e * HM * HM,
            es_b2 + (long)e * HM, b3h, b3l, nullptr,
            b2h, b2l, HM, HM, ce, nullptr, 1.f);
        mma2_gemm<false, OUT_SPLIT, false><<<gH, tb, SMEM_DYN>>>(
            b3h, b3l, wh + WT_ES3 + (long)e * HM * HM, wl + WT_ES3 + (long)e * HM * HM,
            es_b3 + (long)e * HM, b2h, b2l, nullptr,
            nullptr, nullptr, HM, HM, ce, nullptr, 1.f);
        mma2_gemm<false, OUT_SCAT, false><<<gO, tb, SMEM_DYN>>>(
            b2h, b2l, wh + WT_EOUT + (long)e * HM * DM, wl + WT_EOUT + (long)e * HM * DM,
            e_out_b + (long)e * DM, nullptr, nullptr, out,
            nullptr, nullptr, HM, DM, ce, ie, 1.f / EM);
    }
}

// round 8
// speedup vs baseline: 4.1130x; 2.3168x over previous
#include <cuda_runtime.h>
#include <cuda_fp16.h>
#include <math.h>
#include <stdint.h>

// Problem constants
#define NTOK 16384
#define DM   512
#define RHM  1024
#define HM   2048
#define EM   8
#define TOPK 4

// GEMM tile config
#define BM 128
#define BN 128
#define BK 32
#define STAGES 4
#define AROWB 80                        // 64B data + 16B pad
#define BROWB 272                       // 256B data + 16B pad
#define SA_BYTES (128 * AROWB)          // 10240
#define SB_BYTES (32 * BROWB)           // 8704

#define OUT_SPLIT 0
#define OUT_F32   1
#define OUT_SCAT  2
#define OUT_HALF  3

typedef __half fp16;

// ---------------- scratch --------------------------------------------------
__device__ fp16  g_xh[(size_t)NTOK * DM];
__device__ fp16  g_xl[(size_t)NTOK * DM];
__device__ fp16  g_b1h[(size_t)NTOK * HM];
__device__ fp16  g_b1l[(size_t)NTOK * HM];
__device__ fp16  g_b2h[(size_t)NTOK * HM];
__device__ fp16  g_b2l[(size_t)NTOK * HM];
__device__ fp16  g_b3h[(size_t)NTOK * HM];
__device__ fp16  g_b3l[(size_t)NTOK * HM];
__device__ float g_f32[(size_t)NTOK * RHM];
__device__ float g_logits[(size_t)NTOK * EM];
__device__ unsigned g_maskb[NTOK];
__device__ int   g_idx[EM * NTOK];
__device__ int   g_cnt[EM];
// weight copies: router hi/lo, experts hi only
#define WT_RIN  0L
#define WT_RS1  (WT_RIN + 512L * 1024L)
#define WT_RS2  (WT_RS1 + 1024L * 1024L)
#define WT_RS3  (WT_RS2 + 1024L * 1024L)
#define WT_EIN  (WT_RS3 + 1024L * 1024L)
#define WT_ES1  (WT_EIN + 8L * 512L * 2048L)
#define WT_ES2  (WT_ES1 + 8L * 2048L * 2048L)
#define WT_ES3  (WT_ES2 + 8L * 2048L * 2048L)
#define WT_EOUT (WT_ES3 + 8L * 2048L * 2048L)
#define WT_TOTAL (WT_EOUT + 8L * 2048L * 512L)
__device__ fp16 g_wh[WT_TOTAL];
__device__ fp16 g_wl[4L * 1024L * 1024L];   // lo only for router weights

// ---------------- helpers --------------------------------------------------
__device__ __forceinline__ uint32_t smem_u32(const void* p) {
    return (uint32_t)__cvta_generic_to_shared(p);
}
__device__ __forceinline__ void cp16(uint32_t dst, const void* src) {
    asm volatile("cp.async.cg.shared.global [%0], [%1], 16;" :: "r"(dst), "l"(src));
}
__device__ __forceinline__ void cp_commit() {
    asm volatile("cp.async.commit_group;" ::: "memory");
}
__device__ __forceinline__ void cp_wait2() {
    asm volatile("cp.async.wait_group 2;" ::: "memory");
}
__device__ __forceinline__ void ldm_x4(uint32_t* r, uint32_t addr) {
    asm volatile("ldmatrix.sync.aligned.m8n8.x4.shared.b16 {%0,%1,%2,%3},[%4];"
                 : "=r"(r[0]), "=r"(r[1]), "=r"(r[2]), "=r"(r[3]) : "r"(addr));
}
__device__ __forceinline__ void ldm_x4t(uint32_t* r, uint32_t addr) {
    asm volatile("ldmatrix.sync.aligned.m8n8.x4.trans.shared.b16 {%0,%1,%2,%3},[%4];"
                 : "=r"(r[0]), "=r"(r[1]), "=r"(r[2]), "=r"(r[3]) : "r"(addr));
}
__device__ __forceinline__ void mma16816(float* d, const uint32_t* a, const uint32_t* b) {
    asm volatile(
        "mma.sync.aligned.m16n8k16.row.col.f32.f16.f16.f32 "
        "{%0,%1,%2,%3},{%4,%5,%6,%7},{%8,%9},{%0,%1,%2,%3};"
        : "+f"(d[0]), "+f"(d[1]), "+f"(d[2]), "+f"(d[3])
        : "r"(a[0]), "r"(a[1]), "r"(a[2]), "r"(a[3]), "r"(b[0]), "r"(b[1]));
}
__device__ __forceinline__ void split1(float v, fp16& h, fp16& l) {
    h = __float2half_rn(v);
    l = __float2half_rn(v - __half2float(h));
}

// ---------------- pipelined fp16 mma.sync GEMM -----------------------------
// NTERMS=3: C = (AH+AL)(BH+BL) ~ hh+lh+hl.  NTERMS=1: C = AH*BH.
// A K-major, B row-major [K,N] (trans-ldmatrix). 256 thr, warp tile 64x32.
template <int NTERMS, bool GATHER, int OUTMODE, bool SILU>
__global__ void __launch_bounds__(256, 1)
mma2_gemm(const fp16* __restrict__ AH, const fp16* __restrict__ AL,
          const fp16* __restrict__ BH, const fp16* __restrict__ BL,
          const float* __restrict__ bias,
          fp16* __restrict__ OH, fp16* __restrict__ OL,
          float* __restrict__ OF,
          const fp16* __restrict__ XH, const fp16* __restrict__ XL,
          int K, int N,
          const int* __restrict__ mcnt, const int* __restrict__ gidx,
          float scale)
{
    constexpr int NS = (NTERMS == 3) ? 2 : 1;
    constexpr uint32_t OFFB = NS * SA_BYTES;
    constexpr uint32_t STG  = NS * (SA_BYTES + SB_BYTES);

    const int M = mcnt ? *mcnt : NTOK;
    const int m0 = blockIdx.y * BM;
    if (m0 >= M) return;
    const int n0 = blockIdx.x * BN;

    extern __shared__ char sm[];
    const uint32_t sm0 = smem_u32(sm);

    const int tid  = threadIdx.x;
    const int lane = tid & 31;
    const int wid  = tid >> 5;
    const int wm   = wid >> 2;
    const int wn   = wid & 3;

    // ---- load slots ----
    const char* aSrcH[2]; const char* aSrcL[2];
    uint32_t dA[2];
#pragma unroll
    for (int i = 0; i < 2; i++) {
        const int idx = i * 256 + tid;
        const int r = idx >> 2;
        const int g = idx & 3;
        long grow;
        if (GATHER) grow = (m0 + r < M) ? (long)gidx[m0 + r] : 0L;
        else        grow = m0 + r;
        aSrcH[i] = (const char*)(AH + grow * (long)K) + g * 16;
        if (NTERMS == 3) aSrcL[i] = (const char*)(AL + grow * (long)K) + g * 16;
        dA[i] = (uint32_t)(r * AROWB + g * 16);
    }
    const char* bSrcH[2]; const char* bSrcL[2];
    uint32_t dB[2];
#pragma unroll
    for (int i = 0; i < 2; i++) {
        const int idx = i * 256 + tid;
        const int r = idx >> 4;
        const int g = idx & 15;
        bSrcH[i] = (const char*)(BH + (long)r * N + n0) + g * 16;
        if (NTERMS == 3) bSrcL[i] = (const char*)(BL + (long)r * N + n0) + g * 16;
        dB[i] = (uint32_t)(r * BROWB + g * 16);
    }

    float acc[4][4][4];
#pragma unroll
    for (int mi = 0; mi < 4; mi++)
#pragma unroll
        for (int ni = 0; ni < 4; ni++)
#pragma unroll
            for (int q = 0; q < 4; q++) acc[mi][ni][q] = 0.f;

    auto load_stage = [&](int s, int kt) {
        const uint32_t su = sm0 + s * STG;
        const long kA = (long)kt * 64;
        const long kB = (long)kt * BK * N * 2;
#pragma unroll
        for (int i = 0; i < 2; i++) {
            cp16(su + dA[i], aSrcH[i] + kA);
            if (NTERMS == 3) cp16(su + SA_BYTES + dA[i], aSrcL[i] + kA);
        }
#pragma unroll
        for (int i = 0; i < 2; i++) {
            cp16(su + OFFB + dB[i], bSrcH[i] + kB);
            if (NTERMS == 3) cp16(su + OFFB + SB_BYTES + dB[i], bSrcL[i] + kB);
        }
    };

    const int niter = K / BK;
    load_stage(0, 0); cp_commit();
    load_stage(1, 1); cp_commit();
    load_stage(2, 2); cp_commit();

    const uint32_t aOff = (uint32_t)((wm * 64 + (lane & 15)) * AROWB + (lane >> 4) * 16);
    const uint32_t bOff = (uint32_t)(OFFB + (lane & 15) * BROWB
                                     + (wn * 32 + (lane >> 4) * 8) * 2);

    for (int kt = 0; kt < niter; kt++) {
        cp_wait2();
        __syncthreads();
        if (kt + 3 < niter) load_stage((kt + 3) & 3, kt + 3);
        cp_commit();

        const uint32_t su = sm0 + (kt & 3) * STG;
        const uint32_t aH = su + aOff;
        const uint32_t bHb = su + bOff;
#pragma unroll
        for (int k16 = 0; k16 < 2; k16++) {
            uint32_t ah[4][4], al[4][4], bh[4][2], bl[4][2];
#pragma unroll
            for (int mi = 0; mi < 4; mi++) {
                const uint32_t o = (uint32_t)(mi * 16 * AROWB + k16 * 32);
                ldm_x4(ah[mi], aH + o);
                if (NTERMS == 3) ldm_x4(al[mi], aH + SA_BYTES + o);
            }
#pragma unroll
            for (int p = 0; p < 2; p++) {
                const uint32_t o = (uint32_t)(k16 * 16 * BROWB + p * 32);
                uint32_t r[4];
                ldm_x4t(r, bHb + o);
                bh[2 * p][0] = r[0]; bh[2 * p][1] = r[1];
                bh[2 * p + 1][0] = r[2]; bh[2 * p + 1][1] = r[3];
                if (NTERMS == 3) {
                    ldm_x4t(r, bHb + SB_BYTES + o);
                    bl[2 * p][0] = r[0]; bl[2 * p][1] = r[1];
                    bl[2 * p + 1][0] = r[2]; bl[2 * p + 1][1] = r[3];
                }
            }
#pragma unroll
            for (int mi = 0; mi < 4; mi++)
#pragma unroll
                for (int ni = 0; ni < 4; ni++) {
                    mma16816(acc[mi][ni], ah[mi], bh[ni]);
                    if (NTERMS == 3) {
                        mma16816(acc[mi][ni], al[mi], bh[ni]);
                        mma16816(acc[mi][ni], ah[mi], bl[ni]);
                    }
                }
        }
        __syncthreads();
    }

    // ---- epilogue ----
    const int gid = lane >> 2;
    const int qid = lane & 3;
#pragma unroll
    for (int mi = 0; mi < 4; mi++) {
#pragma unroll
        for (int half = 0; half < 2; half++) {
            const int m = m0 + wm * 64 + mi * 16 + gid + half * 8;
            if (m >= M) continue;
            long orow;
            if (OUTMODE == OUT_SCAT) orow = (long)gidx[m] * N;
            else                     orow = (long)m * N;
#pragma unroll
            for (int ni = 0; ni < 4; ni++) {
                const int col = n0 + wn * 32 + ni * 8 + qid * 2;
                float v0 = acc[mi][ni][half * 2 + 0] + bias[col];
                float v1 = acc[mi][ni][half * 2 + 1] + bias[col + 1];
                if (SILU) {
                    const __half2 hh = *(const __half2*)(XH + (long)m * N + col);
                    float a0 = __half2float(hh.x);
                    float a1 = __half2float(hh.y);
                    if (NTERMS == 3) {
                        const __half2 hl = *(const __half2*)(XL + (long)m * N + col);
                        a0 += __half2float(hl.x);
                        a1 += __half2float(hl.y);
                    }
                    v0 *= a0 / (1.f + __expf(-a0));
                    v1 *= a1 / (1.f + __expf(-a1));
                }
                if (OUTMODE == OUT_SPLIT) {
                    fp16 h0, l0, h1, l1;
                    split1(v0, h0, l0); split1(v1, h1, l1);
                    __half2 hv; hv.x = h0; hv.y = h1;
                    __half2 lv; lv.x = l0; lv.y = l1;
                    *(__half2*)(OH + orow + col) = hv;
                    *(__half2*)(OL + orow + col) = lv;
                } else if (OUTMODE == OUT_HALF) {
                    __half2 hv;
                    hv.x = __float2half_rn(v0);
                    hv.y = __float2half_rn(v1);
                    *(__half2*)(OH + orow + col) = hv;
                } else if (OUTMODE == OUT_F32) {
                    OF[orow + col]     = v0;
                    OF[orow + col + 1] = v1;
                } else {
                    OF[orow + col]     += v0 * scale;
                    OF[orow + col + 1] += v1 * scale;
                }
            }
        }
    }
}

// ---------------- fp32 -> fp16 hi/lo split ----------------------------------
__global__ void __launch_bounds__(256)
split_kernel(const float* __restrict__ src, fp16* __restrict__ dh,
             fp16* __restrict__ dl, long n)
{
    const long stride = (long)gridDim.x * blockDim.x * 4;
    for (long i0 = ((long)blockIdx.x * blockDim.x + threadIdx.x) * 4; i0 < n; i0 += stride) {
        const float4 v = *(const float4*)(src + i0);
        fp16 h0, l0, h1, l1, h2, l2, h3, l3;
        split1(v.x, h0, l0); split1(v.y, h1, l1);
        split1(v.z, h2, l2); split1(v.w, h3, l3);
        __half2 ha, hb, la, lb;
        ha.x = h0; ha.y = h1; hb.x = h2; hb.y = h3;
        la.x = l0; la.y = l1; lb.x = l2; lb.y = l3;
        *(__half2*)(dh + i0)     = ha;
        *(__half2*)(dh + i0 + 2) = hb;
        *(__half2*)(dl + i0)     = la;
        *(__half2*)(dl + i0 + 2) = lb;
    }
}

// ---------------- fp32 -> fp16 convert (hi only, expert weights) ------------
__global__ void __launch_bounds__(256)
cvt_kernel(const float* __restrict__ src, fp16* __restrict__ dh, long n)
{
    const long stride = (long)gridDim.x * blockDim.x * 4;
    for (long i0 = ((long)blockIdx.x * blockDim.x + threadIdx.x) * 4; i0 < n; i0 += stride) {
        const float4 v = *(const float4*)(src + i0);
        __half2 ha, hb;
        ha.x = __float2half_rn(v.x); ha.y = __float2half_rn(v.y);
        hb.x = __float2half_rn(v.z); hb.y = __float2half_rn(v.w);
        *(__half2*)(dh + i0)     = ha;
        *(__half2*)(dh + i0 + 2) = hb;
    }
}

// ---------------- small kernels ---------------------------------------------
__global__ void __launch_bounds__(256)
logits_kernel(const float* __restrict__ rh, const float* __restrict__ W,
              const float* __restrict__ b, float* __restrict__ logits)
{
    const int t = blockIdx.x;
    const float* row = rh + (long)t * RHM;
    float p[EM];
#pragma unroll
    for (int e = 0; e < EM; e++) p[e] = 0.f;
    for (int k = threadIdx.x; k < RHM; k += 256) {
        const float v = row[k];
        const float* wr = W + (long)k * EM;
#pragma unroll
        for (int e = 0; e < EM; e++) p[e] = fmaf(v, wr[e], p[e]);
    }
#pragma unroll
    for (int e = 0; e < EM; e++)
#pragma unroll
        for (int off = 16; off > 0; off >>= 1)
            p[e] += __shfl_down_sync(0xffffffffu, p[e], off);
    __shared__ float red[EM][8];
    const int lane = threadIdx.x & 31, warp = threadIdx.x >> 5;
    if (lane == 0)
#pragma unroll
        for (int e = 0; e < EM; e++) red[e][warp] = p[e];
    __syncthreads();
    if (threadIdx.x < EM) {
        float s = b[threadIdx.x];
#pragma unroll
        for (int w = 0; w < 8; w++) s += red[threadIdx.x][w];
        logits[(long)t * EM + threadIdx.x] = s;
    }
}

__global__ void topk_kernel(const float* __restrict__ logits,
                            unsigned* __restrict__ maskb)
{
    const int t = blockIdx.x * blockDim.x + threadIdx.x;
    if (t >= NTOK) return;
    float v[EM];
#pragma unroll
    for (int e = 0; e < EM; e++) v[e] = logits[(long)t * EM + e];
    unsigned m = 0;
#pragma unroll
    for (int s = 0; s < TOPK; s++) {
        int best = 0;
        float bv = -INFINITY;
#pragma unroll
        for (int e = 0; e < EM; e++) {
            if (!((m >> e) & 1u) && v[e] > bv) { bv = v[e]; best = e; }
        }
        m |= 1u << best;
    }
    maskb[t] = m;
}

__global__ void __launch_bounds__(256)
compact_kernel(const unsigned* __restrict__ maskb,
               int* __restrict__ idx, int* __restrict__ cnt)
{
    const int e = blockIdx.x;
    __shared__ int s_base;
    __shared__ int s_warp[8];
    if (threadIdx.x == 0) s_base = 0;
    __syncthreads();
    const int lane = threadIdx.x & 31, warp = threadIdx.x >> 5;
    for (int c = 0; c < NTOK; c += 256) {
        const int t = c + threadIdx.x;
        const int p = (maskb[t] >> e) & 1u;
        const unsigned bal = __ballot_sync(0xffffffffu, p);
        if (lane == 0) s_warp[warp] = __popc(bal);
        __syncthreads();
        int woff = 0, tot = 0;
        for (int w = 0; w < 8; w++) { if (w < warp) woff += s_warp[w]; tot += s_warp[w]; }
        const int rank = __popc(bal & ((1u << lane) - 1u));
        if (p) idx[e * NTOK + s_base + woff + rank] = t;
        __syncthreads();
        if (threadIdx.x == 0) s_base += tot;
        __syncthreads();
    }
    if (threadIdx.x == 0) cnt[e] = s_base;
}

__global__ void zero_kernel(float* __restrict__ out, long n)
{
    const long stride = (long)gridDim.x * blockDim.x;
    for (long i = (long)blockIdx.x * blockDim.x + threadIdx.x; i < n; i += stride)
        out[i] = 0.f;
}

// ---------------- launcher ---------------------------------------------------
extern "C" void kernel_launch(void* const* d_in, const int* in_sizes, int n_in,
                              void* d_out, int out_size)
{
    const float* x       = (const float*)d_in[0];
    const float* r_in_w  = (const float*)d_in[1];
    const float* r_in_b  = (const float*)d_in[2];
    const float* rs_w1   = (const float*)d_in[3];
    const float* rs_b1   = (const float*)d_in[4];
    const float* rs_w2   = (const float*)d_in[5];
    const float* rs_b2   = (const float*)d_in[6];
    const float* rs_w3   = (const float*)d_in[7];
    const float* rs_b3   = (const float*)d_in[8];
    const float* r_out_w = (const float*)d_in[9];
    const float* r_out_b = (const float*)d_in[10];
    const float* e_in_w  = (const float*)d_in[11];
    const float* e_in_b  = (const float*)d_in[12];
    const float* es_w1   = (const float*)d_in[13];
    const float* es_b1   = (const float*)d_in[14];
    const float* es_w2   = (const float*)d_in[15];
    const float* es_b2   = (const float*)d_in[16];
    const float* es_w3   = (const float*)d_in[17];
    const float* es_b3   = (const float*)d_in[18];
    const float* e_out_w = (const float*)d_in[19];
    const float* e_out_b = (const float*)d_in[20];
    float* out = (float*)d_out;

    fp16 *xh, *xl, *b1h, *b1l, *b2h, *b2l, *b3h, *b3l, *wh, *wl;
    float *f32buf, *logits;
    unsigned* maskb;
    int *idx, *cnt;
    cudaGetSymbolAddress((void**)&xh, g_xh);   cudaGetSymbolAddress((void**)&xl, g_xl);
    cudaGetSymbolAddress((void**)&b1h, g_b1h); cudaGetSymbolAddress((void**)&b1l, g_b1l);
    cudaGetSymbolAddress((void**)&b2h, g_b2h); cudaGetSymbolAddress((void**)&b2l, g_b2l);
    cudaGetSymbolAddress((void**)&b3h, g_b3h); cudaGetSymbolAddress((void**)&b3l, g_b3l);
    cudaGetSymbolAddress((void**)&f32buf, g_f32);
    cudaGetSymbolAddress((void**)&logits, g_logits);
    cudaGetSymbolAddress((void**)&maskb, g_maskb);
    cudaGetSymbolAddress((void**)&idx, g_idx);
    cudaGetSymbolAddress((void**)&cnt, g_cnt);
    cudaGetSymbolAddress((void**)&wh, g_wh);
    cudaGetSymbolAddress((void**)&wl, g_wl);

    const int SM3 = STAGES * 2 * (SA_BYTES + SB_BYTES);  // 151552
    const int SM1 = STAGES * (SA_BYTES + SB_BYTES);      // 75776
    cudaFuncSetAttribute(mma2_gemm<3, false, OUT_SPLIT, false>,
                         cudaFuncAttributeMaxDynamicSharedMemorySize, SM3);
    cudaFuncSetAttribute(mma2_gemm<3, false, OUT_SPLIT, true>,
                         cudaFuncAttributeMaxDynamicSharedMemorySize, SM3);
    cudaFuncSetAttribute(mma2_gemm<3, false, OUT_F32, false>,
                         cudaFuncAttributeMaxDynamicSharedMemorySize, SM3);
    cudaFuncSetAttribute(mma2_gemm<1, true, OUT_HALF, false>,
                         cudaFuncAttributeMaxDynamicSharedMemorySize, SM1);
    cudaFuncSetAttribute(mma2_gemm<1, false, OUT_HALF, false>,
                         cudaFuncAttributeMaxDynamicSharedMemorySize, SM1);
    cudaFuncSetAttribute(mma2_gemm<1, false, OUT_HALF, true>,
                         cudaFuncAttributeMaxDynamicSharedMemorySize, SM1);
    cudaFuncSetAttribute(mma2_gemm<1, false, OUT_SCAT, false>,
                         cudaFuncAttributeMaxDynamicSharedMemorySize, SM1);

    const dim3 tb(256);
    const dim3 gR(RHM / BN, NTOK / BM);   // 8 x 128
    const dim3 gH(HM / BN, NTOK / BM);    // 16 x 128
    const dim3 gO(DM / BN, NTOK / BM);    // 4 x 128

    // ---- router (3-term fp16, high precision) ----
    split_kernel<<<512, tb>>>(x, xh, xl, (long)NTOK * DM);
    split_kernel<<<512, tb>>>(r_in_w, wh + WT_RIN, wl + WT_RIN, 512L * 1024L);
    mma2_gemm<3, false, OUT_SPLIT, false><<<gR, tb, SM3>>>(
        xh, xl, wh + WT_RIN, wl + WT_RIN, r_in_b, b1h, b1l, nullptr,
        nullptr, nullptr, DM, RHM, nullptr, nullptr, 1.f);
    split_kernel<<<512, tb>>>(rs_w1, wh + WT_RS1, wl + WT_RS1, 1024L * 1024L);
    mma2_gemm<3, false, OUT_SPLIT, false><<<gR, tb, SM3>>>(
        b1h, b1l, wh + WT_RS1, wl + WT_RS1, rs_b1, b2h, b2l, nullptr,
        nullptr, nullptr, RHM, RHM, nullptr, nullptr, 1.f);
    split_kernel<<<512, tb>>>(rs_w2, wh + WT_RS2, wl + WT_RS2, 1024L * 1024L);
    mma2_gemm<3, false, OUT_SPLIT, true><<<gR, tb, SM3>>>(
        b1h, b1l, wh + WT_RS2, wl + WT_RS2, rs_b2, b3h, b3l, nullptr,
        b2h, b2l, RHM, RHM, nullptr, nullptr, 1.f);
    split_kernel<<<512, tb>>>(rs_w3, wh + WT_RS3, wl + WT_RS3, 1024L * 1024L);
    mma2_gemm<3, false, OUT_F32, false><<<gR, tb, SM3>>>(
        b3h, b3l, wh + WT_RS3, wl + WT_RS3, rs_b3, nullptr, nullptr, f32buf,
        nullptr, nullptr, RHM, RHM, nullptr, nullptr, 1.f);
    logits_kernel<<<NTOK, tb>>>(f32buf, r_out_w, r_out_b, logits);
    topk_kernel<<<NTOK / 256, tb>>>(logits, maskb);
    compact_kernel<<<EM, tb>>>(maskb, idx, cnt);
    zero_kernel<<<1024, tb>>>(out, (long)NTOK * DM);

    // expert weight converts (hi only)
    cvt_kernel<<<2048, tb>>>(e_in_w, wh + WT_EIN, 8L * 512L * 2048L);
    cvt_kernel<<<4096, tb>>>(es_w1, wh + WT_ES1, 8L * 2048L * 2048L);
    cvt_kernel<<<4096, tb>>>(es_w2, wh + WT_ES2, 8L * 2048L * 2048L);
    cvt_kernel<<<4096, tb>>>(es_w3, wh + WT_ES3, 8L * 2048L * 2048L);
    cvt_kernel<<<2048, tb>>>(e_out_w, wh + WT_EOUT, 8L * 2048L * 512L);

    // ---- experts (single-term fp16, selected tokens only) ----
    for (int e = 0; e < EM; e++) {
        const int* ce = cnt + e;
        const int* ie = idx + e * NTOK;
        mma2_gemm<1, true, OUT_HALF, false><<<gH, tb, SM1>>>(
            xh, nullptr, wh + WT_EIN + (long)e * DM * HM, nullptr,
            e_in_b + (long)e * HM, b1h, nullptr, nullptr,
            nullptr, nullptr, DM, HM, ce, ie, 1.f);
        mma2_gemm<1, false, OUT_HALF, false><<<gH, tb, SM1>>>(
            b1h, nullptr, wh + WT_ES1 + (long)e * HM * HM, nullptr,
            es_b1 + (long)e * HM, b2h, nullptr, nullptr,
            nullptr, nullptr, HM, HM, ce, nullptr, 1.f);
        mma2_gemm<1, false, OUT_HALF, true><<<gH, tb, SM1>>>(
            b1h, nullptr, wh + WT_ES2 + (long)e * HM * HM, nullptr,
            es_b2 + (long)e * HM, b3h, nullptr, nullptr,
            b2h, nullptr, HM, HM, ce, nullptr, 1.f);
        mma2_gemm<1, false, OUT_HALF, false><<<gH, tb, SM1>>>(
            b3h, nullptr, wh + WT_ES3 + (long)e * HM * HM, nullptr,
            es_b3 + (long)e * HM, b2h, nullptr, nullptr,
            nullptr, nullptr, HM, HM, ce, nullptr, 1.f);
        mma2_gemm<1, false, OUT_SCAT, false><<<gO, tb, SM1>>>(
            b2h, nullptr, wh + WT_EOUT + (long)e * HM * DM, nullptr,
            e_out_b + (long)e * DM, nullptr, nullptr, out,
            nullptr, nullptr, HM, DM, ce, ie, 1.f / EM);
    }
}

// round 11
// speedup vs baseline: 4.3962x; 1.0689x over previous
#include <cuda_runtime.h>
#include <cuda_fp16.h>
#include <math.h>
#include <stdint.h>

// Problem constants
#define NTOK 16384
#define DM   512
#define RHM  1024
#define HM   2048
#define EM   8
#define TOPK 4

// GEMM tile config
#define BM 128
#define BN 128
#define BK 32
#define STAGES 4
#define AROWB 80
#define BROWB 272
#define SA_BYTES (128 * AROWB)
#define SB_BYTES (32 * BROWB)

#define OUT_SPLIT 0
#define OUT_F32   1
#define OUT_HALF  3
#define OUT_SLOT  4

typedef __half fp16;

// ---------------- scratch --------------------------------------------------
__device__ fp16  g_xh[(size_t)NTOK * DM];
__device__ fp16  g_xl[(size_t)NTOK * DM];
__device__ fp16  g_b1h[(size_t)NTOK * HM];
__device__ fp16  g_b1l[(size_t)NTOK * HM];
__device__ fp16  g_b2h[(size_t)NTOK * HM];
__device__ fp16  g_b2l[(size_t)NTOK * HM];
__device__ fp16  g_b3h[(size_t)NTOK * HM];
__device__ fp16  g_b3l[(size_t)NTOK * HM];
// per-expert activation buffers (z-batched expert launches)
__device__ fp16  g_e1[(size_t)EM * NTOK * HM];
__device__ fp16  g_e2[(size_t)EM * NTOK * HM];
__device__ fp16  g_e3[(size_t)EM * NTOK * HM];
__device__ float g_out4[(size_t)NTOK * TOPK * DM];
__device__ float g_f32[(size_t)NTOK * RHM];
__device__ float g_logits[(size_t)NTOK * EM];
__device__ unsigned g_maskb[NTOK];
__device__ int   g_idx[EM * NTOK];
__device__ int   g_cnt[EM];
// weight copies: router hi/lo, experts hi only
#define WT_RIN  0L
#define WT_RS1  (WT_RIN + 512L * 1024L)
#define WT_RS2  (WT_RS1 + 1024L * 1024L)
#define WT_RS3  (WT_RS2 + 1024L * 1024L)
#define WT_EIN  (WT_RS3 + 1024L * 1024L)
#define WT_ES1  (WT_EIN + 8L * 512L * 2048L)
#define WT_ES2  (WT_ES1 + 8L * 2048L * 2048L)
#define WT_ES3  (WT_ES2 + 8L * 2048L * 2048L)
#define WT_EOUT (WT_ES3 + 8L * 2048L * 2048L)
#define WT_TOTAL (WT_EOUT + 8L * 2048L * 512L)
__device__ fp16 g_wh[WT_TOTAL];
__device__ fp16 g_wl[4L * 1024L * 1024L];

// ---------------- helpers --------------------------------------------------
__device__ __forceinline__ uint32_t smem_u32(const void* p) {
    return (uint32_t)__cvta_generic_to_shared(p);
}
__device__ __forceinline__ void cp16(uint32_t dst, const void* src) {
    asm volatile("cp.async.cg.shared.global [%0], [%1], 16;" :: "r"(dst), "l"(src));
}
__device__ __forceinline__ void cp_commit() {
    asm volatile("cp.async.commit_group;" ::: "memory");
}
__device__ __forceinline__ void cp_wait2() {
    asm volatile("cp.async.wait_group 2;" ::: "memory");
}
__device__ __forceinline__ void ldm_x4(uint32_t* r, uint32_t addr) {
    asm volatile("ldmatrix.sync.aligned.m8n8.x4.shared.b16 {%0,%1,%2,%3},[%4];"
                 : "=r"(r[0]), "=r"(r[1]), "=r"(r[2]), "=r"(r[3]) : "r"(addr));
}
__device__ __forceinline__ void ldm_x4t(uint32_t* r, uint32_t addr) {
    asm volatile("ldmatrix.sync.aligned.m8n8.x4.trans.shared.b16 {%0,%1,%2,%3},[%4];"
                 : "=r"(r[0]), "=r"(r[1]), "=r"(r[2]), "=r"(r[3]) : "r"(addr));
}
__device__ __forceinline__ void mma16816(float* d, const uint32_t* a, const uint32_t* b) {
    asm volatile(
        "mma.sync.aligned.m16n8k16.row.col.f32.f16.f16.f32 "
        "{%0,%1,%2,%3},{%4,%5,%6,%7},{%8,%9},{%0,%1,%2,%3};"
        : "+f"(d[0]), "+f"(d[1]), "+f"(d[2]), "+f"(d[3])
        : "r"(a[0]), "r"(a[1]), "r"(a[2]), "r"(a[3]), "r"(b[0]), "r"(b[1]));
}
__device__ __forceinline__ void split1(float v, fp16& h, fp16& l) {
    h = __float2half_rn(v);
    l = __float2half_rn(v - __half2float(h));
}

// ---------------- pipelined fp16 mma.sync GEMM, z-batched over experts -----
// NTERMS=3: C = (AH+AL)(BH+BL) ~ hh+lh+hl.  NTERMS=1: C = AH*BH.
// Expert ez = blockIdx.z offsets A/B/bias/output by the given strides.
// OUT_SLOT: writes (acc+bias)*scale to OF[(tok*TOPK + slot)*N + col] where
// slot = popc(mask[tok] & ((1<<ez)-1)) — one writer per slot, deterministic.
template <int NTERMS, bool GATHER, int OUTMODE, bool SILU>
__global__ void __launch_bounds__(256, 1)
mma2_gemm(const fp16* __restrict__ AH, const fp16* __restrict__ AL,
          const fp16* __restrict__ BH, const fp16* __restrict__ BL,
          const float* __restrict__ bias,
          fp16* __restrict__ OH, fp16* __restrict__ OL,
          float* __restrict__ OF,
          const fp16* __restrict__ XH, const fp16* __restrict__ XL,
          int K, int N,
          const int* __restrict__ mcnt, const int* __restrict__ gidx,
          const unsigned* __restrict__ mk,
          long aStride, long bStride, int biasStride, long oStride,
          float scale)
{
    constexpr int NS = (NTERMS == 3) ? 2 : 1;
    constexpr uint32_t OFFB = NS * SA_BYTES;
    constexpr uint32_t STG  = NS * (SA_BYTES + SB_BYTES);

    const int ez = blockIdx.z;
    const int M = mcnt ? mcnt[ez] : NTOK;
    const int m0 = blockIdx.y * BM;
    if (m0 >= M) return;
    const int n0 = blockIdx.x * BN;

    AH   += (long)ez * aStride;
    BH   += (long)ez * bStride;
    bias += (long)ez * biasStride;
    if (OUTMODE == OUT_HALF) OH += (long)ez * oStride;
    if (SILU)                XH += (long)ez * oStride;
    if (gidx) gidx += (long)ez * NTOK;

    extern __shared__ char sm[];
    const uint32_t sm0 = smem_u32(sm);

    const int tid  = threadIdx.x;
    const int lane = tid & 31;
    const int wid  = tid >> 5;
    const int wm   = wid >> 2;
    const int wn   = wid & 3;

    const char* aSrcH[2]; const char* aSrcL[2];
    uint32_t dA[2];
#pragma unroll
    for (int i = 0; i < 2; i++) {
        const int idx = i * 256 + tid;
        const int r = idx >> 2;
        const int g = idx & 3;
        long grow;
        if (GATHER) grow = (m0 + r < M) ? (long)gidx[m0 + r] : 0L;
        else        grow = m0 + r;
        aSrcH[i] = (const char*)(AH + grow * (long)K) + g * 16;
        if (NTERMS == 3) aSrcL[i] = (const char*)(AL + grow * (long)K) + g * 16;
        dA[i] = (uint32_t)(r * AROWB + g * 16);
    }
    const char* bSrcH[2]; const char* bSrcL[2];
    uint32_t dB[2];
#pragma unroll
    for (int i = 0; i < 2; i++) {
        const int idx = i * 256 + tid;
        const int r = idx >> 4;
        const int g = idx & 15;
        bSrcH[i] = (const char*)(BH + (long)r * N + n0) + g * 16;
        if (NTERMS == 3) bSrcL[i] = (const char*)(BL + (long)r * N + n0) + g * 16;
        dB[i] = (uint32_t)(r * BROWB + g * 16);
    }

    float acc[4][4][4];
#pragma unroll
    for (int mi = 0; mi < 4; mi++)
#pragma unroll
        for (int ni = 0; ni < 4; ni++)
#pragma unroll
            for (int q = 0; q < 4; q++) acc[mi][ni][q] = 0.f;

    auto load_stage = [&](int s, int kt) {
        const uint32_t su = sm0 + s * STG;
        const long kA = (long)kt * 64;
        const long kB = (long)kt * BK * N * 2;
#pragma unroll
        for (int i = 0; i < 2; i++) {
            cp16(su + dA[i], aSrcH[i] + kA);
            if (NTERMS == 3) cp16(su + SA_BYTES + dA[i], aSrcL[i] + kA);
        }
#pragma unroll
        for (int i = 0; i < 2; i++) {
            cp16(su + OFFB + dB[i], bSrcH[i] + kB);
            if (NTERMS == 3) cp16(su + OFFB + SB_BYTES + dB[i], bSrcL[i] + kB);
        }
    };

    const int niter = K / BK;
    load_stage(0, 0); cp_commit();
    load_stage(1, 1); cp_commit();
    load_stage(2, 2); cp_commit();

    const uint32_t aOff = (uint32_t)((wm * 64 + (lane & 15)) * AROWB + (lane >> 4) * 16);
    const uint32_t bOff = (uint32_t)(OFFB + (lane & 15) * BROWB
                                     + (wn * 32 + (lane >> 4) * 8) * 2);

    for (int kt = 0; kt < niter; kt++) {
        cp_wait2();
        __syncthreads();
        if (kt + 3 < niter) load_stage((kt + 3) & 3, kt + 3);
        cp_commit();

        const uint32_t su = sm0 + (kt & 3) * STG;
        const uint32_t aH = su + aOff;
        const uint32_t bHb = su + bOff;
#pragma unroll
        for (int k16 = 0; k16 < 2; k16++) {
            uint32_t ah[4][4], al[4][4], bh[4][2], bl[4][2];
#pragma unroll
            for (int mi = 0; mi < 4; mi++) {
                const uint32_t o = (uint32_t)(mi * 16 * AROWB + k16 * 32);
                ldm_x4(ah[mi], aH + o);
                if (NTERMS == 3) ldm_x4(al[mi], aH + SA_BYTES + o);
            }
#pragma unroll
            for (int p = 0; p < 2; p++) {
                const uint32_t o = (uint32_t)(k16 * 16 * BROWB + p * 32);
                uint32_t r[4];
                ldm_x4t(r, bHb + o);
                bh[2 * p][0] = r[0]; bh[2 * p][1] = r[1];
                bh[2 * p + 1][0] = r[2]; bh[2 * p + 1][1] = r[3];
                if (NTERMS == 3) {
                    ldm_x4t(r, bHb + SB_BYTES + o);
                    bl[2 * p][0] = r[0]; bl[2 * p][1] = r[1];
                    bl[2 * p + 1][0] = r[2]; bl[2 * p + 1][1] = r[3];
                }
            }
#pragma unroll
            for (int mi = 0; mi < 4; mi++)
#pragma unroll
                for (int ni = 0; ni < 4; ni++) {
                    mma16816(acc[mi][ni], ah[mi], bh[ni]);
                    if (NTERMS == 3) {
                        mma16816(acc[mi][ni], al[mi], bh[ni]);
                        mma16816(acc[mi][ni], ah[mi], bl[ni]);
                    }
                }
        }
        __syncthreads();
    }

    const int gid = lane >> 2;
    const int qid = lane & 3;
#pragma unroll
    for (int mi = 0; mi < 4; mi++) {
#pragma unroll
        for (int half = 0; half < 2; half++) {
            const int m = m0 + wm * 64 + mi * 16 + gid + half * 8;
            if (m >= M) continue;
            long orow;
            if (OUTMODE == OUT_SLOT) {
                const int t = gidx[m];
                const int slot = __popc(mk[t] & ((1u << ez) - 1u));
                orow = ((long)t * TOPK + slot) * N;
            } else {
                orow = (long)m * N;
            }
#pragma unroll
            for (int ni = 0; ni < 4; ni++) {
                const int col = n0 + wn * 32 + ni * 8 + qid * 2;
                float v0 = acc[mi][ni][half * 2 + 0] + bias[col];
                float v1 = acc[mi][ni][half * 2 + 1] + bias[col + 1];
                if (SILU) {
                    const __half2 hh = *(const __half2*)(XH + (long)m * N + col);
                    float a0 = __half2float(hh.x);
                    float a1 = __half2float(hh.y);
                    if (NTERMS == 3) {
                        const __half2 hl = *(const __half2*)(XL + (long)m * N + col);
                        a0 += __half2float(hl.x);
                        a1 += __half2float(hl.y);
                    }
                    v0 *= a0 / (1.f + __expf(-a0));
                    v1 *= a1 / (1.f + __expf(-a1));
                }
                if (OUTMODE == OUT_SPLIT) {
                    fp16 h0, l0, h1, l1;
                    split1(v0, h0, l0); split1(v1, h1, l1);
                    __half2 hv; hv.x = h0; hv.y = h1;
                    __half2 lv; lv.x = l0; lv.y = l1;
                    *(__half2*)(OH + orow + col) = hv;
                    *(__half2*)(OL + orow + col) = lv;
                } else if (OUTMODE == OUT_HALF) {
                    __half2 hv;
                    hv.x = __float2half_rn(v0);
                    hv.y = __float2half_rn(v1);
                    *(__half2*)(OH + orow + col) = hv;
                } else if (OUTMODE == OUT_F32) {
                    OF[orow + col]     = v0;
                    OF[orow + col + 1] = v1;
                } else {  // OUT_SLOT
                    OF[orow + col]     = v0 * scale;
                    OF[orow + col + 1] = v1 * scale;
                }
            }
        }
    }
}

// ---------------- slot reduce: out[t,d] = sum_s out4[t,s,d] -----------------
__global__ void __launch_bounds__(256)
reduce_kernel(const float* __restrict__ out4, float* __restrict__ out)
{
    const long n = (long)NTOK * DM;
    const long stride = (long)gridDim.x * blockDim.x * 4;
    for (long i0 = ((long)blockIdx.x * blockDim.x + threadIdx.x) * 4; i0 < n; i0 += stride) {
        const long t = i0 / DM;
        const long d = i0 - t * DM;
        const float* base = out4 + (t * TOPK) * DM + d;
        float4 s = *(const float4*)(base);
        const float4 s1 = *(const float4*)(base + DM);
        const float4 s2 = *(const float4*)(base + 2 * DM);
        const float4 s3 = *(const float4*)(base + 3 * DM);
        s.x += s1.x + s2.x + s3.x;
        s.y += s1.y + s2.y + s3.y;
        s.z += s1.z + s2.z + s3.z;
        s.w += s1.w + s2.w + s3.w;
        *(float4*)(out + i0) = s;
    }
}

// ---------------- fp32 -> fp16 hi/lo split ----------------------------------
__global__ void __launch_bounds__(256)
split_kernel(const float* __restrict__ src, fp16* __restrict__ dh,
             fp16* __restrict__ dl, long n)
{
    const long stride = (long)gridDim.x * blockDim.x * 4;
    for (long i0 = ((long)blockIdx.x * blockDim.x + threadIdx.x) * 4; i0 < n; i0 += stride) {
        const float4 v = *(const float4*)(src + i0);
        fp16 h0, l0, h1, l1, h2, l2, h3, l3;
        split1(v.x, h0, l0); split1(v.y, h1, l1);
        split1(v.z, h2, l2); split1(v.w, h3, l3);
        __half2 ha, hb, la, lb;
        ha.x = h0; ha.y = h1; hb.x = h2; hb.y = h3;
        la.x = l0; la.y = l1; lb.x = l2; lb.y = l3;
        *(__half2*)(dh + i0)     = ha;
        *(__half2*)(dh + i0 + 2) = hb;
        *(__half2*)(dl + i0)     = la;
        *(__half2*)(dl + i0 + 2) = lb;
    }
}

// ---------------- fp32 -> fp16 convert (hi only) ----------------------------
__global__ void __launch_bounds__(256)
cvt_kernel(const float* __restrict__ src, fp16* __restrict__ dh, long n)
{
    const long stride = (long)gridDim.x * blockDim.x * 4;
    for (long i0 = ((long)blockIdx.x * blockDim.x + threadIdx.x) * 4; i0 < n; i0 += stride) {
        const float4 v = *(const float4*)(src + i0);
        __half2 ha, hb;
        ha.x = __float2half_rn(v.x); ha.y = __float2half_rn(v.y);
        hb.x = __float2half_rn(v.z); hb.y = __float2half_rn(v.w);
        *(__half2*)(dh + i0)     = ha;
        *(__half2*)(dh + i0 + 2) = hb;
    }
}

// ---------------- small kernels ---------------------------------------------
__global__ void __launch_bounds__(256)
logits_kernel(const float* __restrict__ rh, const float* __restrict__ W,
              const float* __restrict__ b, float* __restrict__ logits)
{
    const int t = blockIdx.x;
    const float* row = rh + (long)t * RHM;
    float p[EM];
#pragma unroll
    for (int e = 0; e < EM; e++) p[e] = 0.f;
    for (int k = threadIdx.x; k < RHM; k += 256) {
        const float v = row[k];
        const float* wr = W + (long)k * EM;
#pragma unroll
        for (int e = 0; e < EM; e++) p[e] = fmaf(v, wr[e], p[e]);
    }
#pragma unroll
    for (int e = 0; e < EM; e++)
#pragma unroll
        for (int off = 16; off > 0; off >>= 1)
            p[e] += __shfl_down_sync(0xffffffffu, p[e], off);
    __shared__ float red[EM][8];
    const int lane = threadIdx.x & 31, warp = threadIdx.x >> 5;
    if (lane == 0)
#pragma unroll
        for (int e = 0; e < EM; e++) red[e][warp] = p[e];
    __syncthreads();
    if (threadIdx.x < EM) {
        float s = b[threadIdx.x];
#pragma unroll
        for (int w = 0; w < 8; w++) s += red[threadIdx.x][w];
        logits[(long)t * EM + threadIdx.x] = s;
    }
}

__global__ void topk_kernel(const float* __restrict__ logits,
                            unsigned* __restrict__ maskb)
{
    const int t = blockIdx.x * blockDim.x + threadIdx.x;
    if (t >= NTOK) return;
    float v[EM];
#pragma unroll
    for (int e = 0; e < EM; e++) v[e] = logits[(long)t * EM + e];
    unsigned m = 0;
#pragma unroll
    for (int s = 0; s < TOPK; s++) {
        int best = 0;
        float bv = -INFINITY;
#pragma unroll
        for (int e = 0; e < EM; e++) {
            if (!((m >> e) & 1u) && v[e] > bv) { bv = v[e]; best = e; }
        }
        m |= 1u << best;
    }
    maskb[t] = m;
}

__global__ void __launch_bounds__(256)
compact_kernel(const unsigned* __restrict__ maskb,
               int* __restrict__ idx, int* __restrict__ cnt)
{
    const int e = blockIdx.x;
    __shared__ int s_base;
    __shared__ int s_warp[8];
    if (threadIdx.x == 0) s_base = 0;
    __syncthreads();
    const int lane = threadIdx.x & 31, warp = threadIdx.x >> 5;
    for (int c = 0; c < NTOK; c += 256) {
        const int t = c + threadIdx.x;
        const int p = (maskb[t] >> e) & 1u;
        const unsigned bal = __ballot_sync(0xffffffffu, p);
        if (lane == 0) s_warp[warp] = __popc(bal);
        __syncthreads();
        int woff = 0, tot = 0;
        for (int w = 0; w < 8; w++) { if (w < warp) woff += s_warp[w]; tot += s_warp[w]; }
        const int rank = __popc(bal & ((1u << lane) - 1u));
        if (p) idx[e * NTOK + s_base + woff + rank] = t;
        __syncthreads();
        if (threadIdx.x == 0) s_base += tot;
        __syncthreads();
    }
    if (threadIdx.x == 0) cnt[e] = s_base;
}

// ---------------- launcher ---------------------------------------------------
extern "C" void kernel_launch(void* const* d_in, const int* in_sizes, int n_in,
                              void* d_out, int out_size)
{
    const float* x       = (const float*)d_in[0];
    const float* r_in_w  = (const float*)d_in[1];
    const float* r_in_b  = (const float*)d_in[2];
    const float* rs_w1   = (const float*)d_in[3];
    const float* rs_b1   = (const float*)d_in[4];
    const float* rs_w2   = (const float*)d_in[5];
    const float* rs_b2   = (const float*)d_in[6];
    const float* rs_w3   = (const float*)d_in[7];
    const float* rs_b3   = (const float*)d_in[8];
    const float* r_out_w = (const float*)d_in[9];
    const float* r_out_b = (const float*)d_in[10];
    const float* e_in_w  = (const float*)d_in[11];
    const float* e_in_b  = (const float*)d_in[12];
    const float* es_w1   = (const float*)d_in[13];
    const float* es_b1   = (const float*)d_in[14];
    const float* es_w2   = (const float*)d_in[15];
    const float* es_b2   = (const float*)d_in[16];
    const float* es_w3   = (const float*)d_in[17];
    const float* es_b3   = (const float*)d_in[18];
    const float* e_out_w = (const float*)d_in[19];
    const float* e_out_b = (const float*)d_in[20];
    float* out = (float*)d_out;

    fp16 *xh, *xl, *b1h, *b1l, *b2h, *b2l, *b3h, *b3l, *wh, *wl;
    fp16 *e1, *e2, *e3;
    float *out4, *f32buf, *logits;
    unsigned* maskb;
    int *idx, *cnt;
    cudaGetSymbolAddress((void**)&xh, g_xh);   cudaGetSymbolAddress((void**)&xl, g_xl);
    cudaGetSymbolAddress((void**)&b1h, g_b1h); cudaGetSymbolAddress((void**)&b1l, g_b1l);
    cudaGetSymbolAddress((void**)&b2h, g_b2h); cudaGetSymbolAddress((void**)&b2l, g_b2l);
    cudaGetSymbolAddress((void**)&b3h, g_b3h); cudaGetSymbolAddress((void**)&b3l, g_b3l);
    cudaGetSymbolAddress((void**)&e1, g_e1);
    cudaGetSymbolAddress((void**)&e2, g_e2);
    cudaGetSymbolAddress((void**)&e3, g_e3);
    cudaGetSymbolAddress((void**)&out4, g_out4);
    cudaGetSymbolAddress((void**)&f32buf, g_f32);
    cudaGetSymbolAddress((void**)&logits, g_logits);
    cudaGetSymbolAddress((void**)&maskb, g_maskb);
    cudaGetSymbolAddress((void**)&idx, g_idx);
    cudaGetSymbolAddress((void**)&cnt, g_cnt);
    cudaGetSymbolAddress((void**)&wh, g_wh);
    cudaGetSymbolAddress((void**)&wl, g_wl);

    const int SM3 = STAGES * 2 * (SA_BYTES + SB_BYTES);
    const int SM1 = STAGES * (SA_BYTES + SB_BYTES);
    cudaFuncSetAttribute(mma2_gemm<3, false, OUT_SPLIT, false>,
                         cudaFuncAttributeMaxDynamicSharedMemorySize, SM3);
    cudaFuncSetAttribute(mma2_gemm<3, false, OUT_SPLIT, true>,
                         cudaFuncAttributeMaxDynamicSharedMemorySize, SM3);
    cudaFuncSetAttribute(mma2_gemm<3, false, OUT_F32, false>,
                         cudaFuncAttributeMaxDynamicSharedMemorySize, SM3);
    cudaFuncSetAttribute(mma2_gemm<1, true, OUT_HALF, false>,
                         cudaFuncAttributeMaxDynamicSharedMemorySize, SM1);
    cudaFuncSetAttribute(mma2_gemm<1, false, OUT_HALF, false>,
                         cudaFuncAttributeMaxDynamicSharedMemorySize, SM1);
    cudaFuncSetAttribute(mma2_gemm<1, false, OUT_HALF, true>,
                         cudaFuncAttributeMaxDynamicSharedMemorySize, SM1);
    cudaFuncSetAttribute(mma2_gemm<1, false, OUT_SLOT, false>,
                         cudaFuncAttributeMaxDynamicSharedMemorySize, SM1);

    const dim3 tb(256);
    const dim3 gR(RHM / BN, NTOK / BM, 1);
    const dim3 gHE(HM / BN, NTOK / BM, EM);    // 16 x 128 x 8
    const dim3 gOE(DM / BN, NTOK / BM, EM);    // 4 x 128 x 8

    // ---- router (3-term fp16) ----
    split_kernel<<<512, tb>>>(x, xh, xl, (long)NTOK * DM);
    split_kernel<<<512, tb>>>(r_in_w, wh + WT_RIN, wl + WT_RIN, 512L * 1024L);
    mma2_gemm<3, false, OUT_SPLIT, false><<<gR, tb, SM3>>>(
        xh, xl, wh + WT_RIN, wl + WT_RIN, r_in_b, b1h, b1l, nullptr,
        nullptr, nullptr, DM, RHM, nullptr, nullptr, nullptr, 0, 0, 0, 0, 1.f);
    split_kernel<<<512, tb>>>(rs_w1, wh + WT_RS1, wl + WT_RS1, 1024L * 1024L);
    mma2_gemm<3, false, OUT_SPLIT, false><<<gR, tb, SM3>>>(
        b1h, b1l, wh + WT_RS1, wl + WT_RS1, rs_b1, b2h, b2l, nullptr,
        nullptr, nullptr, RHM, RHM, nullptr, nullptr, nullptr, 0, 0, 0, 0, 1.f);
    split_kernel<<<512, tb>>>(rs_w2, wh + WT_RS2, wl + WT_RS2, 1024L * 1024L);
    mma2_gemm<3, false, OUT_SPLIT, true><<<gR, tb, SM3>>>(
        b1h, b1l, wh + WT_RS2, wl + WT_RS2, rs_b2, b3h, b3l, nullptr,
        b2h, b2l, RHM, RHM, nullptr, nullptr, nullptr, 0, 0, 0, 0, 1.f);
    split_kernel<<<512, tb>>>(rs_w3, wh + WT_RS3, wl + WT_RS3, 1024L * 1024L);
    mma2_gemm<3, false, OUT_F32, false><<<gR, tb, SM3>>>(
        b3h, b3l, wh + WT_RS3, wl + WT_RS3, rs_b3, nullptr, nullptr, f32buf,
        nullptr, nullptr, RHM, RHM, nullptr, nullptr, nullptr, 0, 0, 0, 0, 1.f);
    logits_kernel<<<NTOK, tb>>>(f32buf, r_out_w, r_out_b, logits);
    topk_kernel<<<NTOK / 256, tb>>>(logits, maskb);
    compact_kernel<<<EM, tb>>>(maskb, idx, cnt);

    // ---- expert weight converts (whole arrays, few big launches) ----
    cvt_kernel<<<1024, tb>>>(e_in_w, wh + WT_EIN, 8L * 512L * 2048L);
    cvt_kernel<<<2048, tb>>>(es_w1, wh + WT_ES1, 8L * 2048L * 2048L);
    cvt_kernel<<<2048, tb>>>(es_w2, wh + WT_ES2, 8L * 2048L * 2048L);
    cvt_kernel<<<2048, tb>>>(es_w3, wh + WT_ES3, 8L * 2048L * 2048L);
    cvt_kernel<<<1024, tb>>>(e_out_w, wh + WT_EOUT, 8L * 2048L * 512L);

    // ---- experts: 5 z-batched launches (all 8 experts concurrent) ----
    const long NH = (long)NTOK * HM;
    mma2_gemm<1, true, OUT_HALF, false><<<gHE, tb, SM1>>>(
        xh, nullptr, wh + WT_EIN, nullptr, e_in_b, e1, nullptr, nullptr,
        nullptr, nullptr, DM, HM, cnt, idx, nullptr,
        0, (long)DM * HM, HM, NH, 1.f);
    mma2_gemm<1, false, OUT_HALF, false><<<gHE, tb, SM1>>>(
        e1, nullptr, wh + WT_ES1, nullptr, es_b1, e2, nullptr, nullptr,
        nullptr, nullptr, HM, HM, cnt, nullptr, nullptr,
        NH, (long)HM * HM, HM, NH, 1.f);
    mma2_gemm<1, false, OUT_HALF, true><<<gHE, tb, SM1>>>(
        e1, nullptr, wh + WT_ES2, nullptr, es_b2, e3, nullptr, nullptr,
        e2, nullptr, HM, HM, cnt, nullptr, nullptr,
        NH, (long)HM * HM, HM, NH, 1.f);
    mma2_gemm<1, false, OUT_HALF, false><<<gHE, tb, SM1>>>(
        e3, nullptr, wh + WT_ES3, nullptr, es_b3, e2, nullptr, nullptr,
        nullptr, nullptr, HM, HM, cnt, nullptr, nullptr,
        NH, (long)HM * HM, HM, NH, 1.f);
    mma2_gemm<1, false, OUT_SLOT, false><<<gOE, tb, SM1>>>(
        e2, nullptr, wh + WT_EOUT, nullptr, e_out_b, nullptr, nullptr, out4,
        nullptr, nullptr, HM, DM, cnt, idx, maskb,
        NH, (long)HM * DM, DM, 0, 1.f / EM);

    // ---- deterministic 4-slot reduction ----
    reduce_kernel<<<1024, tb>>>(out4, out);
}

// round 13
// speedup vs baseline: 5.2044x; 1.1838x over previous
#include <cuda_runtime.h>
#include <cuda_fp16.h>
#include <math.h>
#include <stdint.h>

// Problem constants
#define NTOK 16384
#define DM   512
#define RHM  1024
#define HM   2048
#define EM   8
#define TOPK 4

// GEMM tile config
#define BM 128
#define BN 128
#define BK 32
#define STAGES 4
#define AROWB 80
#define BROWB 272
#define SA_BYTES (128 * AROWB)
#define SB_BYTES (32 * BROWB)

#define OUT_SPLIT 0
#define OUT_F32   1
#define OUT_HALF  3
#define OUT_SLOT  4

typedef __half fp16;

// ---------------- scratch --------------------------------------------------
__device__ fp16  g_xh[(size_t)NTOK * DM];
__device__ fp16  g_xl[(size_t)NTOK * DM];
__device__ fp16  g_b1h[(size_t)NTOK * HM];
__device__ fp16  g_b1l[(size_t)NTOK * HM];
__device__ fp16  g_b2h[(size_t)NTOK * HM];
__device__ fp16  g_b2l[(size_t)NTOK * HM];
__device__ fp16  g_b3h[(size_t)NTOK * HM];
__device__ fp16  g_b3l[(size_t)NTOK * HM];
// per-expert activation buffers (z-batched expert launches)
__device__ fp16  g_e1[(size_t)EM * NTOK * HM];
__device__ fp16  g_e2[(size_t)EM * NTOK * HM];
__device__ fp16  g_e3[(size_t)EM * NTOK * HM];
__device__ float g_out4[(size_t)NTOK * TOPK * DM];
__device__ float g_f32[(size_t)NTOK * RHM];
__device__ float g_logits[(size_t)NTOK * EM];
__device__ unsigned g_maskb[NTOK];
__device__ int   g_idx[EM * NTOK];
__device__ int   g_cnt[EM];
// weight copies: router hi/lo, experts hi only
#define WT_RIN  0L
#define WT_RS1  (WT_RIN + 512L * 1024L)
#define WT_RS2  (WT_RS1 + 1024L * 1024L)
#define WT_RS3  (WT_RS2 + 1024L * 1024L)
#define WT_EIN  (WT_RS3 + 1024L * 1024L)
#define WT_ES1  (WT_EIN + 8L * 512L * 2048L)
#define WT_ES2  (WT_ES1 + 8L * 2048L * 2048L)
#define WT_ES3  (WT_ES2 + 8L * 2048L * 2048L)
#define WT_EOUT (WT_ES3 + 8L * 2048L * 2048L)
#define WT_TOTAL (WT_EOUT + 8L * 2048L * 512L)
__device__ fp16 g_wh[WT_TOTAL];
__device__ fp16 g_wl[4L * 1024L * 1024L];

// ---------------- helpers --------------------------------------------------
__device__ __forceinline__ uint32_t smem_u32(const void* p) {
    return (uint32_t)__cvta_generic_to_shared(p);
}
__device__ __forceinline__ void cp16(uint32_t dst, const void* src) {
    asm volatile("cp.async.cg.shared.global [%0], [%1], 16;" :: "r"(dst), "l"(src));
}
__device__ __forceinline__ void cp_commit() {
    asm volatile("cp.async.commit_group;" ::: "memory");
}
__device__ __forceinline__ void cp_wait2() {
    asm volatile("cp.async.wait_group 2;" ::: "memory");
}
__device__ __forceinline__ void ldm_x4(uint32_t* r, uint32_t addr) {
    asm volatile("ldmatrix.sync.aligned.m8n8.x4.shared.b16 {%0,%1,%2,%3},[%4];"
                 : "=r"(r[0]), "=r"(r[1]), "=r"(r[2]), "=r"(r[3]) : "r"(addr));
}
__device__ __forceinline__ void ldm_x4t(uint32_t* r, uint32_t addr) {
    asm volatile("ldmatrix.sync.aligned.m8n8.x4.trans.shared.b16 {%0,%1,%2,%3},[%4];"
                 : "=r"(r[0]), "=r"(r[1]), "=r"(r[2]), "=r"(r[3]) : "r"(addr));
}
__device__ __forceinline__ void mma16816(float* d, const uint32_t* a, const uint32_t* b) {
    asm volatile(
        "mma.sync.aligned.m16n8k16.row.col.f32.f16.f16.f32 "
        "{%0,%1,%2,%3},{%4,%5,%6,%7},{%8,%9},{%0,%1,%2,%3};"
        : "+f"(d[0]), "+f"(d[1]), "+f"(d[2]), "+f"(d[3])
        : "r"(a[0]), "r"(a[1]), "r"(a[2]), "r"(a[3]), "r"(b[0]), "r"(b[1]));
}
__device__ __forceinline__ void split1(float v, fp16& h, fp16& l) {
    h = __float2half_rn(v);
    l = __float2half_rn(v - __half2float(h));
}

// ---------------- pipelined fp16 mma.sync GEMM, z-batched over experts -----
// NTERMS=3: C = (AH+AL)(BH+BL) ~ hh+lh+hl.  NTERMS=1: C = AH*BH.
// Expert ez = blockIdx.z offsets A/B/bias/output by the given strides.
// OUT_SLOT: writes (acc+bias)*scale to OF[(tok*TOPK + slot)*N + col] where
// slot = popc(mask[tok] & ((1<<ez)-1)) — one writer per slot, deterministic.
// Single barrier per K-iter: the barrier after cp_wait2 at iter kt already
// orders all warps past iter kt-1's reads of stage (kt-1)&3 == (kt+3)&3,
// so overwriting it is safe; compute targets distinct stage kt&3.
template <int NTERMS, bool GATHER, int OUTMODE, bool SILU>
__global__ void __launch_bounds__(256, (NTERMS == 1) ? 2 : 1)
mma2_gemm(const fp16* __restrict__ AH, const fp16* __restrict__ AL,
          const fp16* __restrict__ BH, const fp16* __restrict__ BL,
          const float* __restrict__ bias,
          fp16* __restrict__ OH, fp16* __restrict__ OL,
          float* __restrict__ OF,
          const fp16* __restrict__ XH, const fp16* __restrict__ XL,
          int K, int N,
          const int* __restrict__ mcnt, const int* __restrict__ gidx,
          const unsigned* __restrict__ mk,
          long aStride, long bStride, int biasStride, long oStride,
          float scale)
{
    constexpr int NS = (NTERMS == 3) ? 2 : 1;
    constexpr uint32_t OFFB = NS * SA_BYTES;
    constexpr uint32_t STG  = NS * (SA_BYTES + SB_BYTES);

    const int ez = blockIdx.z;
    const int M = mcnt ? mcnt[ez] : NTOK;
    const int m0 = blockIdx.y * BM;
    if (m0 >= M) return;
    const int n0 = blockIdx.x * BN;

    AH   += (long)ez * aStride;
    BH   += (long)ez * bStride;
    bias += (long)ez * biasStride;
    if (OUTMODE == OUT_HALF) OH += (long)ez * oStride;
    if (SILU)                XH += (long)ez * oStride;
    if (gidx) gidx += (long)ez * NTOK;

    extern __shared__ char sm[];
    const uint32_t sm0 = smem_u32(sm);

    const int tid  = threadIdx.x;
    const int lane = tid & 31;
    const int wid  = tid >> 5;
    const int wm   = wid >> 2;
    const int wn   = wid & 3;

    const char* aSrcH[2]; const char* aSrcL[2];
    uint32_t dA[2];
#pragma unroll
    for (int i = 0; i < 2; i++) {
        const int idx = i * 256 + tid;
        const int r = idx >> 2;
        const int g = idx & 3;
        long grow;
        if (GATHER) grow = (m0 + r < M) ? (long)gidx[m0 + r] : 0L;
        else        grow = m0 + r;
        aSrcH[i] = (const char*)(AH + grow * (long)K) + g * 16;
        if (NTERMS == 3) aSrcL[i] = (const char*)(AL + grow * (long)K) + g * 16;
        dA[i] = (uint32_t)(r * AROWB + g * 16);
    }
    const char* bSrcH[2]; const char* bSrcL[2];
    uint32_t dB[2];
#pragma unroll
    for (int i = 0; i < 2; i++) {
        const int idx = i * 256 + tid;
        const int r = idx >> 4;
        const int g = idx & 15;
        bSrcH[i] = (const char*)(BH + (long)r * N + n0) + g * 16;
        if (NTERMS == 3) bSrcL[i] = (const char*)(BL + (long)r * N + n0) + g * 16;
        dB[i] = (uint32_t)(r * BROWB + g * 16);
    }

    float acc[4][4][4];
#pragma unroll
    for (int mi = 0; mi < 4; mi++)
#pragma unroll
        for (int ni = 0; ni < 4; ni++)
#pragma unroll
            for (int q = 0; q < 4; q++) acc[mi][ni][q] = 0.f;

    auto load_stage = [&](int s, int kt) {
        const uint32_t su = sm0 + s * STG;
        const long kA = (long)kt * 64;
        const long kB = (long)kt * BK * N * 2;
#pragma unroll
        for (int i = 0; i < 2; i++) {
            cp16(su + dA[i], aSrcH[i] + kA);
            if (NTERMS == 3) cp16(su + SA_BYTES + dA[i], aSrcL[i] + kA);
        }
#pragma unroll
        for (int i = 0; i < 2; i++) {
            cp16(su + OFFB + dB[i], bSrcH[i] + kB);
            if (NTERMS == 3) cp16(su + OFFB + SB_BYTES + dB[i], bSrcL[i] + kB);
        }
    };

    const int niter = K / BK;
    load_stage(0, 0); cp_commit();
    load_stage(1, 1); cp_commit();
    load_stage(2, 2); cp_commit();

    const uint32_t aOff = (uint32_t)((wm * 64 + (lane & 15)) * AROWB + (lane >> 4) * 16);
    const uint32_t bOff = (uint32_t)(OFFB + (lane & 15) * BROWB
                                     + (wn * 32 + (lane >> 4) * 8) * 2);

    for (int kt = 0; kt < niter; kt++) {
        cp_wait2();
        __syncthreads();
        if (kt + 3 < niter) load_stage((kt + 3) & 3, kt + 3);
        cp_commit();

        const uint32_t su = sm0 + (kt & 3) * STG;
        const uint32_t aH = su + aOff;
        const uint32_t bHb = su + bOff;
#pragma unroll
        for (int k16 = 0; k16 < 2; k16++) {
            uint32_t ah[4][4], al[4][4], bh[4][2], bl[4][2];
#pragma unroll
            for (int mi = 0; mi < 4; mi++) {
                const uint32_t o = (uint32_t)(mi * 16 * AROWB + k16 * 32);
                ldm_x4(ah[mi], aH + o);
                if (NTERMS == 3) ldm_x4(al[mi], aH + SA_BYTES + o);
            }
#pragma unroll
            for (int p = 0; p < 2; p++) {
                const uint32_t o = (uint32_t)(k16 * 16 * BROWB + p * 32);
                uint32_t r[4];
                ldm_x4t(r, bHb + o);
                bh[2 * p][0] = r[0]; bh[2 * p][1] = r[1];
                bh[2 * p + 1][0] = r[2]; bh[2 * p + 1][1] = r[3];
                if (NTERMS == 3) {
                    ldm_x4t(r, bHb + SB_BYTES + o);
                    bl[2 * p][0] = r[0]; bl[2 * p][1] = r[1];
                    bl[2 * p + 1][0] = r[2]; bl[2 * p + 1][1] = r[3];
                }
            }
#pragma unroll
            for (int mi = 0; mi < 4; mi++)
#pragma unroll
                for (int ni = 0; ni < 4; ni++) {
                    mma16816(acc[mi][ni], ah[mi], bh[ni]);
                    if (NTERMS == 3) {
                        mma16816(acc[mi][ni], al[mi], bh[ni]);
                        mma16816(acc[mi][ni], ah[mi], bl[ni]);
                    }
                }
        }
        // no trailing __syncthreads: next iter's top barrier provides the
        // cross-warp ordering before stage reuse (see kernel comment).
    }

    const int gid = lane >> 2;
    const int qid = lane & 3;
#pragma unroll
    for (int mi = 0; mi < 4; mi++) {
#pragma unroll
        for (int half = 0; half < 2; half++) {
            const int m = m0 + wm * 64 + mi * 16 + gid + half * 8;
            if (m >= M) continue;
            long orow;
            if (OUTMODE == OUT_SLOT) {
                const int t = gidx[m];
                const int slot = __popc(mk[t] & ((1u << ez) - 1u));
                orow = ((long)t * TOPK + slot) * N;
            } else {
                orow = (long)m * N;
            }
#pragma unroll
            for (int ni = 0; ni < 4; ni++) {
                const int col = n0 + wn * 32 + ni * 8 + qid * 2;
                float v0 = acc[mi][ni][half * 2 + 0] + bias[col];
                float v1 = acc[mi][ni][half * 2 + 1] + bias[col + 1];
                if (SILU) {
                    const __half2 hh = *(const __half2*)(XH + (long)m * N + col);
                    float a0 = __half2float(hh.x);
                    float a1 = __half2float(hh.y);
                    if (NTERMS == 3) {
                        const __half2 hl = *(const __half2*)(XL + (long)m * N + col);
                        a0 += __half2float(hl.x);
                        a1 += __half2float(hl.y);
                    }
                    v0 *= a0 / (1.f + __expf(-a0));
                    v1 *= a1 / (1.f + __expf(-a1));
                }
                if (OUTMODE == OUT_SPLIT) {
                    fp16 h0, l0, h1, l1;
                    split1(v0, h0, l0); split1(v1, h1, l1);
                    __half2 hv; hv.x = h0; hv.y = h1;
                    __half2 lv; lv.x = l0; lv.y = l1;
                    *(__half2*)(OH + orow + col) = hv;
                    *(__half2*)(OL + orow + col) = lv;
                } else if (OUTMODE == OUT_HALF) {
                    __half2 hv;
                    hv.x = __float2half_rn(v0);
                    hv.y = __float2half_rn(v1);
                    *(__half2*)(OH + orow + col) = hv;
                } else if (OUTMODE == OUT_F32) {
                    OF[orow + col]     = v0;
                    OF[orow + col + 1] = v1;
                } else {  // OUT_SLOT
                    OF[orow + col]     = v0 * scale;
                    OF[orow + col + 1] = v1 * scale;
                }
            }
        }
    }
}

// ---------------- slot reduce: out[t,d] = sum_s out4[t,s,d] -----------------
__global__ void __launch_bounds__(256)
reduce_kernel(const float* __restrict__ out4, float* __restrict__ out)
{
    const long n = (long)NTOK * DM;
    const long stride = (long)gridDim.x * blockDim.x * 4;
    for (long i0 = ((long)blockIdx.x * blockDim.x + threadIdx.x) * 4; i0 < n; i0 += stride) {
        const long t = i0 / DM;
        const long d = i0 - t * DM;
        const float* base = out4 + (t * TOPK) * DM + d;
        float4 s = *(const float4*)(base);
        const float4 s1 = *(const float4*)(base + DM);
        const float4 s2 = *(const float4*)(base + 2 * DM);
        const float4 s3 = *(const float4*)(base + 3 * DM);
        s.x += s1.x + s2.x + s3.x;
        s.y += s1.y + s2.y + s3.y;
        s.z += s1.z + s2.z + s3.z;
        s.w += s1.w + s2.w + s3.w;
        *(float4*)(out + i0) = s;
    }
}

// ---------------- fp32 -> fp16 hi/lo split ----------------------------------
__global__ void __launch_bounds__(256)
split_kernel(const float* __restrict__ src, fp16* __restrict__ dh,
             fp16* __restrict__ dl, long n)
{
    const long stride = (long)gridDim.x * blockDim.x * 4;
    for (long i0 = ((long)blockIdx.x * blockDim.x + threadIdx.x) * 4; i0 < n; i0 += stride) {
        const float4 v = *(const float4*)(src + i0);
        fp16 h0, l0, h1, l1, h2, l2, h3, l3;
        split1(v.x, h0, l0); split1(v.y, h1, l1);
        split1(v.z, h2, l2); split1(v.w, h3, l3);
        __half2 ha, hb, la, lb;
        ha.x = h0; ha.y = h1; hb.x = h2; hb.y = h3;
        la.x = l0; la.y = l1; lb.x = l2; lb.y = l3;
        *(__half2*)(dh + i0)     = ha;
        *(__half2*)(dh + i0 + 2) = hb;
        *(__half2*)(dl + i0)     = la;
        *(__half2*)(dl + i0 + 2) = lb;
    }
}

// ---------------- fp32 -> fp16 convert (hi only) ----------------------------
__global__ void __launch_bounds__(256)
cvt_kernel(const float* __restrict__ src, fp16* __restrict__ dh, long n)
{
    const long stride = (long)gridDim.x * blockDim.x * 4;
    for (long i0 = ((long)blockIdx.x * blockDim.x + threadIdx.x) * 4; i0 < n; i0 += stride) {
        const float4 v = *(const float4*)(src + i0);
        __half2 ha, hb;
        ha.x = __float2half_rn(v.x); ha.y = __float2half_rn(v.y);
        hb.x = __float2half_rn(v.z); hb.y = __float2half_rn(v.w);
        *(__half2*)(dh + i0)     = ha;
        *(__half2*)(dh + i0 + 2) = hb;
    }
}

// ---------------- small kernels ---------------------------------------------
__global__ void __launch_bounds__(256)
logits_kernel(const float* __restrict__ rh, const float* __restrict__ W,
              const float* __restrict__ b, float* __restrict__ logits)
{
    const int t = blockIdx.x;
    const float* row = rh + (long)t * RHM;
    float p[EM];
#pragma unroll
    for (int e = 0; e < EM; e++) p[e] = 0.f;
    for (int k = threadIdx.x; k < RHM; k += 256) {
        const float v = row[k];
        const float* wr = W + (long)k * EM;
#pragma unroll
        for (int e = 0; e < EM; e++) p[e] = fmaf(v, wr[e], p[e]);
    }
#pragma unroll
    for (int e = 0; e < EM; e++)
#pragma unroll
        for (int off = 16; off > 0; off >>= 1)
            p[e] += __shfl_down_sync(0xffffffffu, p[e], off);
    __shared__ float red[EM][8];
    const int lane = threadIdx.x & 31, warp = threadIdx.x >> 5;
    if (lane == 0)
#pragma unroll
        for (int e = 0; e < EM; e++) red[e][warp] = p[e];
    __syncthreads();
    if (threadIdx.x < EM) {
        float s = b[threadIdx.x];
#pragma unroll
        for (int w = 0; w < 8; w++) s += red[threadIdx.x][w];
        logits[(long)t * EM + threadIdx.x] = s;
    }
}

__global__ void topk_kernel(const float* __restrict__ logits,
                            unsigned* __restrict__ maskb)
{
    const int t = blockIdx.x * blockDim.x + threadIdx.x;
    if (t >= NTOK) return;
    float v[EM];
#pragma unroll
    for (int e = 0; e < EM; e++) v[e] = logits[(long)t * EM + e];
    unsigned m = 0;
#pragma unroll
    for (int s = 0; s < TOPK; s++) {
        int best = 0;
        float bv = -INFINITY;
#pragma unroll
        for (int e = 0; e < EM; e++) {
            if (!((m >> e) & 1u) && v[e] > bv) { bv = v[e]; best = e; }
        }
        m |= 1u << best;
    }
    maskb[t] = m;
}

__global__ void __launch_bounds__(256)
compact_kernel(const unsigned* __restrict__ maskb,
               int* __restrict__ idx, int* __restrict__ cnt)
{
    const int e = blockIdx.x;
    __shared__ int s_base;
    __shared__ int s_warp[8];
    if (threadIdx.x == 0) s_base = 0;
    __syncthreads();
    const int lane = threadIdx.x & 31, warp = threadIdx.x >> 5;
    for (int c = 0; c < NTOK; c += 256) {
        const int t = c + threadIdx.x;
        const int p = (maskb[t] >> e) & 1u;
        const unsigned bal = __ballot_sync(0xffffffffu, p);
        if (lane == 0) s_warp[warp] = __popc(bal);
        __syncthreads();
        int woff = 0, tot = 0;
        for (int w = 0; w < 8; w++) { if (w < warp) woff += s_warp[w]; tot += s_warp[w]; }
        const int rank = __popc(bal & ((1u << lane) - 1u));
        if (p) idx[e * NTOK + s_base + woff + rank] = t;
        __syncthreads();
        if (threadIdx.x == 0) s_base += tot;
        __syncthreads();
    }
    if (threadIdx.x == 0) cnt[e] = s_base;
}

// ---------------- launcher ---------------------------------------------------
extern "C" void kernel_launch(void* const* d_in, const int* in_sizes, int n_in,
                              void* d_out, int out_size)
{
    const float* x       = (const float*)d_in[0];
    const float* r_in_w  = (const float*)d_in[1];
    const float* r_in_b  = (const float*)d_in[2];
    const float* rs_w1   = (const float*)d_in[3];
    const float* rs_b1   = (const float*)d_in[4];
    const float* rs_w2   = (const float*)d_in[5];
    const float* rs_b2   = (const float*)d_in[6];
    const float* rs_w3   = (const float*)d_in[7];
    const float* rs_b3   = (const float*)d_in[8];
    const float* r_out_w = (const float*)d_in[9];
    const float* r_out_b = (const float*)d_in[10];
    const float* e_in_w  = (const float*)d_in[11];
    const float* e_in_b  = (const float*)d_in[12];
    const float* es_w1   = (const float*)d_in[13];
    const float* es_b1   = (const float*)d_in[14];
    const float* es_w2   = (const float*)d_in[15];
    const float* es_b2   = (const float*)d_in[16];
    const float* es_w3   = (const float*)d_in[17];
    const float* es_b3   = (const float*)d_in[18];
    const float* e_out_w = (const float*)d_in[19];
    const float* e_out_b = (const float*)d_in[20];
    float* out = (float*)d_out;

    fp16 *xh, *xl, *b1h, *b1l, *b2h, *b2l, *b3h, *b3l, *wh, *wl;
    fp16 *e1, *e2, *e3;
    float *out4, *f32buf, *logits;
    unsigned* maskb;
    int *idx, *cnt;
    cudaGetSymbolAddress((void**)&xh, g_xh);   cudaGetSymbolAddress((void**)&xl, g_xl);
    cudaGetSymbolAddress((void**)&b1h, g_b1h); cudaGetSymbolAddress((void**)&b1l, g_b1l);
    cudaGetSymbolAddress((void**)&b2h, g_b2h); cudaGetSymbolAddress((void**)&b2l, g_b2l);
    cudaGetSymbolAddress((void**)&b3h, g_b3h); cudaGetSymbolAddress((void**)&b3l, g_b3l);
    cudaGetSymbolAddress((void**)&e1, g_e1);
    cudaGetSymbolAddress((void**)&e2, g_e2);
    cudaGetSymbolAddress((void**)&e3, g_e3);
    cudaGetSymbolAddress((void**)&out4, g_out4);
    cudaGetSymbolAddress((void**)&f32buf, g_f32);
    cudaGetSymbolAddress((void**)&logits, g_logits);
    cudaGetSymbolAddress((void**)&maskb, g_maskb);
    cudaGetSymbolAddress((void**)&idx, g_idx);
    cudaGetSymbolAddress((void**)&cnt, g_cnt);
    cudaGetSymbolAddress((void**)&wh, g_wh);
    cudaGetSymbolAddress((void**)&wl, g_wl);

    const int SM3 = STAGES * 2 * (SA_BYTES + SB_BYTES);
    const int SM1 = STAGES * (SA_BYTES + SB_BYTES);
    cudaFuncSetAttribute(mma2_gemm<3, false, OUT_SPLIT, false>,
                         cudaFuncAttributeMaxDynamicSharedMemorySize, SM3);
    cudaFuncSetAttribute(mma2_gemm<3, false, OUT_SPLIT, true>,
                         cudaFuncAttributeMaxDynamicSharedMemorySize, SM3);
    cudaFuncSetAttribute(mma2_gemm<3, false, OUT_F32, false>,
                         cudaFuncAttributeMaxDynamicSharedMemorySize, SM3);
    cudaFuncSetAttribute(mma2_gemm<1, true, OUT_HALF, false>,
                         cudaFuncAttributeMaxDynamicSharedMemorySize, SM1);
    cudaFuncSetAttribute(mma2_gemm<1, false, OUT_HALF, false>,
                         cudaFuncAttributeMaxDynamicSharedMemorySize, SM1);
    cudaFuncSetAttribute(mma2_gemm<1, false, OUT_HALF, true>,
                         cudaFuncAttributeMaxDynamicSharedMemorySize, SM1);
    cudaFuncSetAttribute(mma2_gemm<1, false, OUT_SLOT, false>,
                         cudaFuncAttributeMaxDynamicSharedMemorySize, SM1);

    const dim3 tb(256);
    const dim3 gR(RHM / BN, NTOK / BM, 1);
    const dim3 gHE(HM / BN, NTOK / BM, EM);    // 16 x 128 x 8
    const dim3 gOE(DM / BN, NTOK / BM, EM);    // 4 x 128 x 8

    // ---- router (3-term fp16) ----
    split_kernel<<<512, tb>>>(x, xh, xl, (long)NTOK * DM);
    split_kernel<<<512, tb>>>(r_in_w, wh + WT_RIN, wl + WT_RIN, 512L * 1024L);
    mma2_gemm<3, false, OUT_SPLIT, false><<<gR, tb, SM3>>>(
        xh, xl, wh + WT_RIN, wl + WT_RIN, r_in_b, b1h, b1l, nullptr,
        nullptr, nullptr, DM, RHM, nullptr, nullptr, nullptr, 0, 0, 0, 0, 1.f);
    split_kernel<<<512, tb>>>(rs_w1, wh + WT_RS1, wl + WT_RS1, 1024L * 1024L);
    mma2_gemm<3, false, OUT_SPLIT, false><<<gR, tb, SM3>>>(
        b1h, b1l, wh + WT_RS1, wl + WT_RS1, rs_b1, b2h, b2l, nullptr,
        nullptr, nullptr, RHM, RHM, nullptr, nullptr, nullptr, 0, 0, 0, 0, 1.f);
    split_kernel<<<512, tb>>>(rs_w2, wh + WT_RS2, wl + WT_RS2, 1024L * 1024L);
    mma2_gemm<3, false, OUT_SPLIT, true><<<gR, tb, SM3>>>(
        b1h, b1l, wh + WT_RS2, wl + WT_RS2, rs_b2, b3h, b3l, nullptr,
        b2h, b2l, RHM, RHM, nullptr, nullptr, nullptr, 0, 0, 0, 0, 1.f);
    split_kernel<<<512, tb>>>(rs_w3, wh + WT_RS3, wl + WT_RS3, 1024L * 1024L);
    mma2_gemm<3, false, OUT_F32, false><<<gR, tb, SM3>>>(
        b3h, b3l, wh + WT_RS3, wl + WT_RS3, rs_b3, nullptr, nullptr, f32buf,
        nullptr, nullptr, RHM, RHM, nullptr, nullptr, nullptr, 0, 0, 0, 0, 1.f);
    logits_kernel<<<NTOK, tb>>>(f32buf, r_out_w, r_out_b, logits);
    topk_kernel<<<NTOK / 256, tb>>>(logits, maskb);
    compact_kernel<<<EM, tb>>>(maskb, idx, cnt);

    // ---- expert weight converts ----
    cvt_kernel<<<1024, tb>>>(e_in_w, wh + WT_EIN, 8L * 512L * 2048L);
    cvt_kernel<<<2048, tb>>>(es_w1, wh + WT_ES1, 8L * 2048L * 2048L);
    cvt_kernel<<<2048, tb>>>(es_w2, wh + WT_ES2, 8L * 2048L * 2048L);
    cvt_kernel<<<2048, tb>>>(es_w3, wh + WT_ES3, 8L * 2048L * 2048L);
    cvt_kernel<<<1024, tb>>>(e_out_w, wh + WT_EOUT, 8L * 2048L * 512L);

    // ---- experts: 5 z-batched launches (all 8 experts concurrent) ----
    const long NH = (long)NTOK * HM;
    mma2_gemm<1, true, OUT_HALF, false><<<gHE, tb, SM1>>>(
        xh, nullptr, wh + WT_EIN, nullptr, e_in_b, e1, nullptr, nullptr,
        nullptr, nullptr, DM, HM, cnt, idx, nullptr,
        0, (long)DM * HM, HM, NH, 1.f);
    mma2_gemm<1, false, OUT_HALF, false><<<gHE, tb, SM1>>>(
        e1, nullptr, wh + WT_ES1, nullptr, es_b1, e2, nullptr, nullptr,
        nullptr, nullptr, HM, HM, cnt, nullptr, nullptr,
        NH, (long)HM * HM, HM, NH, 1.f);
    mma2_gemm<1, false, OUT_HALF, true><<<gHE, tb, SM1>>>(
        e1, nullptr, wh + WT_ES2, nullptr, es_b2, e3, nullptr, nullptr,
        e2, nullptr, HM, HM, cnt, nullptr, nullptr,
        NH, (long)HM * HM, HM, NH, 1.f);
    mma2_gemm<1, false, OUT_HALF, false><<<gHE, tb, SM1>>>(
        e3, nullptr, wh + WT_ES3, nullptr, es_b3, e2, nullptr, nullptr,
        nullptr, nullptr, HM, HM, cnt, nullptr, nullptr,
        NH, (long)HM * HM, HM, NH, 1.f);
    mma2_gemm<1, false, OUT_SLOT, false><<<gOE, tb, SM1>>>(
        e2, nullptr, wh + WT_EOUT, nullptr, e_out_b, nullptr, nullptr, out4,
        nullptr, nullptr, HM, DM, cnt, idx, maskb,
        NH, (long)HM * DM, DM, 0, 1.f / EM);

    // ---- deterministic 4-slot reduction ----
    reduce_kernel<<<1024, tb>>>(out4, out);
}

// round 14
// speedup vs baseline: 5.5433x; 1.0651x over previous
#include <cuda_runtime.h>
#include <cuda_fp16.h>
#include <math.h>
#include <stdint.h>

// Problem constants
#define NTOK 16384
#define DM   512
#define RHM  1024
#define HM   2048
#define EM   8
#define TOPK 4

// GEMM tile config
#define BM 128
#define BN 128
#define BK 32
#define STAGES 4
#define AROWB 80
#define BROWB 272
#define SA_BYTES (128 * AROWB)
#define SB_BYTES (32 * BROWB)

#define OUT_SPLIT 0
#define OUT_F32   1
#define OUT_HALF  3
#define OUT_SLOT  4

typedef __half fp16;

// ---------------- scratch --------------------------------------------------
__device__ fp16  g_xh[(size_t)NTOK * DM];
__device__ fp16  g_xl[(size_t)NTOK * DM];
__device__ fp16  g_b1h[(size_t)NTOK * HM];
__device__ fp16  g_b1l[(size_t)NTOK * HM];
__device__ fp16  g_b2h[(size_t)NTOK * HM];
__device__ fp16  g_b2l[(size_t)NTOK * HM];
__device__ fp16  g_b3h[(size_t)NTOK * HM];
__device__ fp16  g_b3l[(size_t)NTOK * HM];
// per-expert activation buffers (z-batched expert launches)
__device__ fp16  g_e1[(size_t)EM * NTOK * HM];
__device__ fp16  g_e2[(size_t)EM * NTOK * HM];
__device__ fp16  g_e3[(size_t)EM * NTOK * HM];
__device__ float g_out4[(size_t)NTOK * TOPK * DM];
__device__ float g_f32[(size_t)NTOK * RHM];
__device__ float g_logits[(size_t)NTOK * EM];
__device__ unsigned g_maskb[NTOK];
__device__ int   g_idx[EM * NTOK];
__device__ int   g_cnt[EM];
// weight copies: router hi/lo, experts hi only
#define WT_RIN  0L
#define WT_RS1  (WT_RIN + 512L * 1024L)
#define WT_RS2  (WT_RS1 + 1024L * 1024L)
#define WT_RS3  (WT_RS2 + 1024L * 1024L)
#define WT_EIN  (WT_RS3 + 1024L * 1024L)
#define WT_ES1  (WT_EIN + 8L * 512L * 2048L)
#define WT_ES2  (WT_ES1 + 8L * 2048L * 2048L)
#define WT_ES3  (WT_ES2 + 8L * 2048L * 2048L)
#define WT_EOUT (WT_ES3 + 8L * 2048L * 2048L)
#define WT_TOTAL (WT_EOUT + 8L * 2048L * 512L)
__device__ fp16 g_wh[WT_TOTAL];
__device__ fp16 g_wl[4L * 1024L * 1024L];

// ---------------- helpers --------------------------------------------------
__device__ __forceinline__ uint32_t smem_u32(const void* p) {
    return (uint32_t)__cvta_generic_to_shared(p);
}
__device__ __forceinline__ void cp16(uint32_t dst, const void* src) {
    asm volatile("cp.async.cg.shared.global [%0], [%1], 16;" :: "r"(dst), "l"(src));
}
__device__ __forceinline__ void cp_commit() {
    asm volatile("cp.async.commit_group;" ::: "memory");
}
__device__ __forceinline__ void cp_wait2() {
    asm volatile("cp.async.wait_group 2;" ::: "memory");
}
__device__ __forceinline__ void ldm_x4(uint32_t* r, uint32_t addr) {
    asm volatile("ldmatrix.sync.aligned.m8n8.x4.shared.b16 {%0,%1,%2,%3},[%4];"
                 : "=r"(r[0]), "=r"(r[1]), "=r"(r[2]), "=r"(r[3]) : "r"(addr));
}
__device__ __forceinline__ void ldm_x4t(uint32_t* r, uint32_t addr) {
    asm volatile("ldmatrix.sync.aligned.m8n8.x4.trans.shared.b16 {%0,%1,%2,%3},[%4];"
                 : "=r"(r[0]), "=r"(r[1]), "=r"(r[2]), "=r"(r[3]) : "r"(addr));
}
__device__ __forceinline__ void mma16816(float* d, const uint32_t* a, const uint32_t* b) {
    asm volatile(
        "mma.sync.aligned.m16n8k16.row.col.f32.f16.f16.f32 "
        "{%0,%1,%2,%3},{%4,%5,%6,%7},{%8,%9},{%0,%1,%2,%3};"
        : "+f"(d[0]), "+f"(d[1]), "+f"(d[2]), "+f"(d[3])
        : "r"(a[0]), "r"(a[1]), "r"(a[2]), "r"(a[3]), "r"(b[0]), "r"(b[1]));
}
__device__ __forceinline__ void split1(float v, fp16& h, fp16& l) {
    h = __float2half_rn(v);
    l = __float2half_rn(v - __half2float(h));
}

// ============================================================================
// 3-term router GEMM: 256 threads, 8 warps, warp tile 64x32 (unchanged)
// ============================================================================
template <int OUTMODE, bool SILU>
__global__ void __launch_bounds__(256, 1)
mma3_gemm(const fp16* __restrict__ AH, const fp16* __restrict__ AL,
          const fp16* __restrict__ BH, const fp16* __restrict__ BL,
          const float* __restrict__ bias,
          fp16* __restrict__ OH, fp16* __restrict__ OL,
          float* __restrict__ OF,
          const fp16* __restrict__ XH, const fp16* __restrict__ XL,
          int K, int N)
{
    constexpr uint32_t OFFB = 2 * SA_BYTES;
    constexpr uint32_t STG  = 2 * (SA_BYTES + SB_BYTES);

    const int m0 = blockIdx.y * BM;
    const int n0 = blockIdx.x * BN;

    extern __shared__ char sm[];
    const uint32_t sm0 = smem_u32(sm);

    const int tid  = threadIdx.x;
    const int lane = tid & 31;
    const int wid  = tid >> 5;
    const int wm   = wid >> 2;
    const int wn   = wid & 3;

    const char* aSrcH[2]; const char* aSrcL[2];
    uint32_t dA[2];
#pragma unroll
    for (int i = 0; i < 2; i++) {
        const int idx = i * 256 + tid;
        const int r = idx >> 2;
        const int g = idx & 3;
        const long grow = m0 + r;
        aSrcH[i] = (const char*)(AH + grow * (long)K) + g * 16;
        aSrcL[i] = (const char*)(AL + grow * (long)K) + g * 16;
        dA[i] = (uint32_t)(r * AROWB + g * 16);
    }
    const char* bSrcH[2]; const char* bSrcL[2];
    uint32_t dB[2];
#pragma unroll
    for (int i = 0; i < 2; i++) {
        const int idx = i * 256 + tid;
        const int r = idx >> 4;
        const int g = idx & 15;
        bSrcH[i] = (const char*)(BH + (long)r * N + n0) + g * 16;
        bSrcL[i] = (const char*)(BL + (long)r * N + n0) + g * 16;
        dB[i] = (uint32_t)(r * BROWB + g * 16);
    }

    float acc[4][4][4];
#pragma unroll
    for (int mi = 0; mi < 4; mi++)
#pragma unroll
        for (int ni = 0; ni < 4; ni++)
#pragma unroll
            for (int q = 0; q < 4; q++) acc[mi][ni][q] = 0.f;

    auto load_stage = [&](int s, int kt) {
        const uint32_t su = sm0 + s * STG;
        const long kA = (long)kt * 64;
        const long kB = (long)kt * BK * N * 2;
#pragma unroll
        for (int i = 0; i < 2; i++) {
            cp16(su + dA[i], aSrcH[i] + kA);
            cp16(su + SA_BYTES + dA[i], aSrcL[i] + kA);
        }
#pragma unroll
        for (int i = 0; i < 2; i++) {
            cp16(su + OFFB + dB[i], bSrcH[i] + kB);
            cp16(su + OFFB + SB_BYTES + dB[i], bSrcL[i] + kB);
        }
    };

    const int niter = K / BK;
    load_stage(0, 0); cp_commit();
    load_stage(1, 1); cp_commit();
    load_stage(2, 2); cp_commit();

    const uint32_t aOff = (uint32_t)((wm * 64 + (lane & 15)) * AROWB + (lane >> 4) * 16);
    const uint32_t bOff = (uint32_t)(OFFB + (lane & 15) * BROWB
                                     + (wn * 32 + (lane >> 4) * 8) * 2);

    for (int kt = 0; kt < niter; kt++) {
        cp_wait2();
        __syncthreads();
        if (kt + 3 < niter) load_stage((kt + 3) & 3, kt + 3);
        cp_commit();

        const uint32_t su = sm0 + (kt & 3) * STG;
        const uint32_t aH = su + aOff;
        const uint32_t bHb = su + bOff;
#pragma unroll
        for (int k16 = 0; k16 < 2; k16++) {
            uint32_t ah[4][4], al[4][4], bh[4][2], bl[4][2];
#pragma unroll
            for (int mi = 0; mi < 4; mi++) {
                const uint32_t o = (uint32_t)(mi * 16 * AROWB + k16 * 32);
                ldm_x4(ah[mi], aH + o);
                ldm_x4(al[mi], aH + SA_BYTES + o);
            }
#pragma unroll
            for (int p = 0; p < 2; p++) {
                const uint32_t o = (uint32_t)(k16 * 16 * BROWB + p * 32);
                uint32_t r[4];
                ldm_x4t(r, bHb + o);
                bh[2 * p][0] = r[0]; bh[2 * p][1] = r[1];
                bh[2 * p + 1][0] = r[2]; bh[2 * p + 1][1] = r[3];
                ldm_x4t(r, bHb + SB_BYTES + o);
                bl[2 * p][0] = r[0]; bl[2 * p][1] = r[1];
                bl[2 * p + 1][0] = r[2]; bl[2 * p + 1][1] = r[3];
            }
#pragma unroll
            for (int mi = 0; mi < 4; mi++)
#pragma unroll
                for (int ni = 0; ni < 4; ni++) {
                    mma16816(acc[mi][ni], ah[mi], bh[ni]);
                    mma16816(acc[mi][ni], al[mi], bh[ni]);
                    mma16816(acc[mi][ni], ah[mi], bl[ni]);
                }
        }
    }

    const int gid = lane >> 2;
    const int qid = lane & 3;
#pragma unroll
    for (int mi = 0; mi < 4; mi++) {
#pragma unroll
        for (int half = 0; half < 2; half++) {
            const int m = m0 + wm * 64 + mi * 16 + gid + half * 8;
            const long orow = (long)m * N;
#pragma unroll
            for (int ni = 0; ni < 4; ni++) {
                const int col = n0 + wn * 32 + ni * 8 + qid * 2;
                float v0 = acc[mi][ni][half * 2 + 0] + bias[col];
                float v1 = acc[mi][ni][half * 2 + 1] + bias[col + 1];
                if (SILU) {
                    const __half2 hh = *(const __half2*)(XH + (long)m * N + col);
                    const __half2 hl = *(const __half2*)(XL + (long)m * N + col);
                    float a0 = __half2float(hh.x) + __half2float(hl.x);
                    float a1 = __half2float(hh.y) + __half2float(hl.y);
                    v0 *= a0 / (1.f + __expf(-a0));
                    v1 *= a1 / (1.f + __expf(-a1));
                }
                if (OUTMODE == OUT_SPLIT) {
                    fp16 h0, l0, h1, l1;
                    split1(v0, h0, l0); split1(v1, h1, l1);
                    __half2 hv; hv.x = h0; hv.y = h1;
                    __half2 lv; lv.x = l0; lv.y = l1;
                    *(__half2*)(OH + orow + col) = hv;
                    *(__half2*)(OL + orow + col) = lv;
                } else {
                    OF[orow + col]     = v0;
                    OF[orow + col + 1] = v1;
                }
            }
        }
    }
}

// ============================================================================
// 1-term expert GEMM: 128 threads, 4 warps, warp tile 64x64, 2 CTAs/SM.
// Higher MMA:LDSM ratio (32 HMMA per 8 ldmatrix per k16 vs 16 per 6).
// Single barrier per K-iter (same proof as before: top barrier at iter kt
// orders all reads of stage (kt-1)&3 == (kt+3)&3 before its overwrite).
// ============================================================================
template <bool GATHER, int OUTMODE, bool SILU>
__global__ void __launch_bounds__(128, 2)
mma1_gemm(const fp16* __restrict__ AH, const fp16* __restrict__ BH,
          const float* __restrict__ bias,
          fp16* __restrict__ OH, float* __restrict__ OF,
          const fp16* __restrict__ XH,
          int K, int N,
          const int* __restrict__ mcnt, const int* __restrict__ gidx,
          const unsigned* __restrict__ mk,
          long aStride, long bStride, int biasStride, long oStride,
          float scale)
{
    constexpr uint32_t STG = SA_BYTES + SB_BYTES;

    const int ez = blockIdx.z;
    const int M = mcnt ? mcnt[ez] : NTOK;
    const int m0 = blockIdx.y * BM;
    if (m0 >= M) return;
    const int n0 = blockIdx.x * BN;

    AH   += (long)ez * aStride;
    BH   += (long)ez * bStride;
    bias += (long)ez * biasStride;
    if (OUTMODE == OUT_HALF) OH += (long)ez * oStride;
    if (SILU)                XH += (long)ez * oStride;
    if (gidx) gidx += (long)ez * NTOK;

    extern __shared__ char sm[];
    const uint32_t sm0 = smem_u32(sm);

    const int tid  = threadIdx.x;
    const int lane = tid & 31;
    const int wid  = tid >> 5;    // 0..3
    const int wm   = wid >> 1;    // 0..1
    const int wn   = wid & 1;     // 0..1

    const char* aSrc[4];
    uint32_t dA[4];
#pragma unroll
    for (int i = 0; i < 4; i++) {
        const int idx = i * 128 + tid;     // 0..511
        const int r = idx >> 2;            // 0..127
        const int g = idx & 3;
        long grow;
        if (GATHER) grow = (m0 + r < M) ? (long)gidx[m0 + r] : 0L;
        else        grow = m0 + r;
        aSrc[i] = (const char*)(AH + grow * (long)K) + g * 16;
        dA[i] = (uint32_t)(r * AROWB + g * 16);
    }
    const char* bSrc[4];
    uint32_t dB[4];
#pragma unroll
    for (int i = 0; i < 4; i++) {
        const int idx = i * 128 + tid;
        const int r = idx >> 4;            // 0..31
        const int g = idx & 15;
        bSrc[i] = (const char*)(BH + (long)r * N + n0) + g * 16;
        dB[i] = (uint32_t)(r * BROWB + g * 16);
    }

    float acc[4][8][4];
#pragma unroll
    for (int mi = 0; mi < 4; mi++)
#pragma unroll
        for (int ni = 0; ni < 8; ni++)
#pragma unroll
            for (int q = 0; q < 4; q++) acc[mi][ni][q] = 0.f;

    auto load_stage = [&](int s, int kt) {
        const uint32_t su = sm0 + s * STG;
        const long kA = (long)kt * 64;
        const long kB = (long)kt * BK * N * 2;
#pragma unroll
        for (int i = 0; i < 4; i++) cp16(su + dA[i], aSrc[i] + kA);
#pragma unroll
        for (int i = 0; i < 4; i++) cp16(su + SA_BYTES + dB[i], bSrc[i] + kB);
    };

    const int niter = K / BK;
    load_stage(0, 0); cp_commit();
    load_stage(1, 1); cp_commit();
    load_stage(2, 2); cp_commit();

    const uint32_t aOff = (uint32_t)((wm * 64 + (lane & 15)) * AROWB + (lane >> 4) * 16);
    const uint32_t bOff = (uint32_t)(SA_BYTES + (lane & 15) * BROWB
                                     + (wn * 64 + (lane >> 4) * 8) * 2);

    for (int kt = 0; kt < niter; kt++) {
        cp_wait2();
        __syncthreads();
        if (kt + 3 < niter) load_stage((kt + 3) & 3, kt + 3);
        cp_commit();

        const uint32_t su = sm0 + (kt & 3) * STG;
        const uint32_t aBase = su + aOff;
        const uint32_t bBase = su + bOff;
#pragma unroll
        for (int k16 = 0; k16 < 2; k16++) {
            uint32_t ah[4][4], bh[8][2];
#pragma unroll
            for (int mi = 0; mi < 4; mi++)
                ldm_x4(ah[mi], aBase + (uint32_t)(mi * 16 * AROWB + k16 * 32));
#pragma unroll
            for (int p = 0; p < 4; p++) {
                uint32_t r[4];
                ldm_x4t(r, bBase + (uint32_t)(k16 * 16 * BROWB + p * 32));
                bh[2 * p][0] = r[0]; bh[2 * p][1] = r[1];
                bh[2 * p + 1][0] = r[2]; bh[2 * p + 1][1] = r[3];
            }
#pragma unroll
            for (int mi = 0; mi < 4; mi++)
#pragma unroll
                for (int ni = 0; ni < 8; ni++)
                    mma16816(acc[mi][ni], ah[mi], bh[ni]);
        }
    }

    const int gid = lane >> 2;
    const int qid = lane & 3;
#pragma unroll
    for (int mi = 0; mi < 4; mi++) {
#pragma unroll
        for (int half = 0; half < 2; half++) {
            const int m = m0 + wm * 64 + mi * 16 + gid + half * 8;
            if (m >= M) continue;
            long orow;
            if (OUTMODE == OUT_SLOT) {
                const int t = gidx[m];
                const int slot = __popc(mk[t] & ((1u << ez) - 1u));
                orow = ((long)t * TOPK + slot) * N;
            } else {
                orow = (long)m * N;
            }
#pragma unroll
            for (int ni = 0; ni < 8; ni++) {
                const int col = n0 + wn * 64 + ni * 8 + qid * 2;
                float v0 = acc[mi][ni][half * 2 + 0] + bias[col];
                float v1 = acc[mi][ni][half * 2 + 1] + bias[col + 1];
                if (SILU) {
                    const __half2 hh = *(const __half2*)(XH + (long)m * N + col);
                    const float a0 = __half2float(hh.x);
                    const float a1 = __half2float(hh.y);
                    v0 *= a0 / (1.f + __expf(-a0));
                    v1 *= a1 / (1.f + __expf(-a1));
                }
                if (OUTMODE == OUT_HALF) {
                    __half2 hv;
                    hv.x = __float2half_rn(v0);
                    hv.y = __float2half_rn(v1);
                    *(__half2*)(OH + orow + col) = hv;
                } else {  // OUT_SLOT
                    OF[orow + col]     = v0 * scale;
                    OF[orow + col + 1] = v1 * scale;
                }
            }
        }
    }
}

// ---------------- slot reduce: out[t,d] = sum_s out4[t,s,d] -----------------
__global__ void __launch_bounds__(256)
reduce_kernel(const float* __restrict__ out4, float* __restrict__ out)
{
    const long n = (long)NTOK * DM;
    const long stride = (long)gridDim.x * blockDim.x * 4;
    for (long i0 = ((long)blockIdx.x * blockDim.x + threadIdx.x) * 4; i0 < n; i0 += stride) {
        const long t = i0 / DM;
        const long d = i0 - t * DM;
        const float* base = out4 + (t * TOPK) * DM + d;
        float4 s = *(const float4*)(base);
        const float4 s1 = *(const float4*)(base + DM);
        const float4 s2 = *(const float4*)(base + 2 * DM);
        const float4 s3 = *(const float4*)(base + 3 * DM);
        s.x += s1.x + s2.x + s3.x;
        s.y += s1.y + s2.y + s3.y;
        s.z += s1.z + s2.z + s3.z;
        s.w += s1.w + s2.w + s3.w;
        *(float4*)(out + i0) = s;
    }
}

// ---------------- fp32 -> fp16 hi/lo split ----------------------------------
__global__ void __launch_bounds__(256)
split_kernel(const float* __restrict__ src, fp16* __restrict__ dh,
             fp16* __restrict__ dl, long n)
{
    const long stride = (long)gridDim.x * blockDim.x * 4;
    for (long i0 = ((long)blockIdx.x * blockDim.x + threadIdx.x) * 4; i0 < n; i0 += stride) {
        const float4 v = *(const float4*)(src + i0);
        fp16 h0, l0, h1, l1, h2, l2, h3, l3;
        split1(v.x, h0, l0); split1(v.y, h1, l1);
        split1(v.z, h2, l2); split1(v.w, h3, l3);
        __half2 ha, hb, la, lb;
        ha.x = h0; ha.y = h1; hb.x = h2; hb.y = h3;
        la.x = l0; la.y = l1; lb.x = l2; lb.y = l3;
        *(__half2*)(dh + i0)     = ha;
        *(__half2*)(dh + i0 + 2) = hb;
        *(__half2*)(dl + i0)     = la;
        *(__half2*)(dl + i0 + 2) = lb;
    }
}

// ---------------- fp32 -> fp16 convert (hi only) ----------------------------
__global__ void __launch_bounds__(256)
cvt_kernel(const float* __restrict__ src, fp16* __restrict__ dh, long n)
{
    const long stride = (long)gridDim.x * blockDim.x * 4;
    for (long i0 = ((long)blockIdx.x * blockDim.x + threadIdx.x) * 4; i0 < n; i0 += stride) {
        const float4 v = *(const float4*)(src + i0);
        __half2 ha, hb;
        ha.x = __float2half_rn(v.x); ha.y = __float2half_rn(v.y);
        hb.x = __float2half_rn(v.z); hb.y = __float2half_rn(v.w);
        *(__half2*)(dh + i0)     = ha;
        *(__half2*)(dh + i0 + 2) = hb;
    }
}

// ---------------- small kernels ---------------------------------------------
__global__ void __launch_bounds__(256)
logits_kernel(const float* __restrict__ rh, const float* __restrict__ W,
              const float* __restrict__ b, float* __restrict__ logits)
{
    const int t = blockIdx.x;
    const float* row = rh + (long)t * RHM;
    float p[EM];
#pragma unroll
    for (int e = 0; e < EM; e++) p[e] = 0.f;
    for (int k = threadIdx.x; k < RHM; k += 256) {
        const float v = row[k];
        const float* wr = W + (long)k * EM;
#pragma unroll
        for (int e = 0; e < EM; e++) p[e] = fmaf(v, wr[e], p[e]);
    }
#pragma unroll
    for (int e = 0; e < EM; e++)
#pragma unroll
        for (int off = 16; off > 0; off >>= 1)
            p[e] += __shfl_down_sync(0xffffffffu, p[e], off);
    __shared__ float red[EM][8];
    const int lane = threadIdx.x & 31, warp = threadIdx.x >> 5;
    if (lane == 0)
#pragma unroll
        for (int e = 0; e < EM; e++) red[e][warp] = p[e];
    __syncthreads();
    if (threadIdx.x < EM) {
        float s = b[threadIdx.x];
#pragma unroll
        for (int w = 0; w < 8; w++) s += red[threadIdx.x][w];
        logits[(long)t * EM + threadIdx.x] = s;
    }
}

__global__ void topk_kernel(const float* __restrict__ logits,
                            unsigned* __restrict__ maskb)
{
    const int t = blockIdx.x * blockDim.x + threadIdx.x;
    if (t >= NTOK) return;
    float v[EM];
#pragma unroll
    for (int e = 0; e < EM; e++) v[e] = logits[(long)t * EM + e];
    unsigned m = 0;
#pragma unroll
    for (int s = 0; s < TOPK; s++) {
        int best = 0;
        float bv = -INFINITY;
#pragma unroll
        for (int e = 0; e < EM; e++) {
            if (!((m >> e) & 1u) && v[e] > bv) { bv = v[e]; best = e; }
        }
        m |= 1u << best;
    }
    maskb[t] = m;
}

__global__ void __launch_bounds__(256)
compact_kernel(const unsigned* __restrict__ maskb,
               int* __restrict__ idx, int* __restrict__ cnt)
{
    const int e = blockIdx.x;
    __shared__ int s_base;
    __shared__ int s_warp[8];
    if (threadIdx.x == 0) s_base = 0;
    __syncthreads();
    const int lane = threadIdx.x & 31, warp = threadIdx.x >> 5;
    for (int c = 0; c < NTOK; c += 256) {
        const int t = c + threadIdx.x;
        const int p = (maskb[t] >> e) & 1u;
        const unsigned bal = __ballot_sync(0xffffffffu, p);
        if (lane == 0) s_warp[warp] = __popc(bal);
        __syncthreads();
        int woff = 0, tot = 0;
        for (int w = 0; w < 8; w++) { if (w < warp) woff += s_warp[w]; tot += s_warp[w]; }
        const int rank = __popc(bal & ((1u << lane) - 1u));
        if (p) idx[e * NTOK + s_base + woff + rank] = t;
        __syncthreads();
        if (threadIdx.x == 0) s_base += tot;
        __syncthreads();
    }
    if (threadIdx.x == 0) cnt[e] = s_base;
}

// ---------------- launcher ---------------------------------------------------
extern "C" void kernel_launch(void* const* d_in, const int* in_sizes, int n_in,
                              void* d_out, int out_size)
{
    const float* x       = (const float*)d_in[0];
    const float* r_in_w  = (const float*)d_in[1];
    const float* r_in_b  = (const float*)d_in[2];
    const float* rs_w1   = (const float*)d_in[3];
    const float* rs_b1   = (const float*)d_in[4];
    const float* rs_w2   = (const float*)d_in[5];
    const float* rs_b2   = (const float*)d_in[6];
    const float* rs_w3   = (const float*)d_in[7];
    const float* rs_b3   = (const float*)d_in[8];
    const float* r_out_w = (const float*)d_in[9];
    const float* r_out_b = (const float*)d_in[10];
    const float* e_in_w  = (const float*)d_in[11];
    const float* e_in_b  = (const float*)d_in[12];
    const float* es_w1   = (const float*)d_in[13];
    const float* es_b1   = (const float*)d_in[14];
    const float* es_w2   = (const float*)d_in[15];
    const float* es_b2   = (const float*)d_in[16];
    const float* es_w3   = (const float*)d_in[17];
    const float* es_b3   = (const float*)d_in[18];
    const float* e_out_w = (const float*)d_in[19];
    const float* e_out_b = (const float*)d_in[20];
    float* out = (float*)d_out;

    fp16 *xh, *xl, *b1h, *b1l, *b2h, *b2l, *b3h, *b3l, *wh, *wl;
    fp16 *e1, *e2, *e3;
    float *out4, *f32buf, *logits;
    unsigned* maskb;
    int *idx, *cnt;
    cudaGetSymbolAddress((void**)&xh, g_xh);   cudaGetSymbolAddress((void**)&xl, g_xl);
    cudaGetSymbolAddress((void**)&b1h, g_b1h); cudaGetSymbolAddress((void**)&b1l, g_b1l);
    cudaGetSymbolAddress((void**)&b2h, g_b2h); cudaGetSymbolAddress((void**)&b2l, g_b2l);
    cudaGetSymbolAddress((void**)&b3h, g_b3h); cudaGetSymbolAddress((void**)&b3l, g_b3l);
    cudaGetSymbolAddress((void**)&e1, g_e1);
    cudaGetSymbolAddress((void**)&e2, g_e2);
    cudaGetSymbolAddress((void**)&e3, g_e3);
    cudaGetSymbolAddress((void**)&out4, g_out4);
    cudaGetSymbolAddress((void**)&f32buf, g_f32);
    cudaGetSymbolAddress((void**)&logits, g_logits);
    cudaGetSymbolAddress((void**)&maskb, g_maskb);
    cudaGetSymbolAddress((void**)&idx, g_idx);
    cudaGetSymbolAddress((void**)&cnt, g_cnt);
    cudaGetSymbolAddress((void**)&wh, g_wh);
    cudaGetSymbolAddress((void**)&wl, g_wl);

    const int SM3 = STAGES * 2 * (SA_BYTES + SB_BYTES);
    const int SM1 = STAGES * (SA_BYTES + SB_BYTES);
    cudaFuncSetAttribute(mma3_gemm<OUT_SPLIT, false>,
                         cudaFuncAttributeMaxDynamicSharedMemorySize, SM3);
    cudaFuncSetAttribute(mma3_gemm<OUT_SPLIT, true>,
                         cudaFuncAttributeMaxDynamicSharedMemorySize, SM3);
    cudaFuncSetAttribute(mma3_gemm<OUT_F32, false>,
                         cudaFuncAttributeMaxDynamicSharedMemorySize, SM3);
    cudaFuncSetAttribute(mma1_gemm<true, OUT_HALF, false>,
                         cudaFuncAttributeMaxDynamicSharedMemorySize, SM1);
    cudaFuncSetAttribute(mma1_gemm<false, OUT_HALF, false>,
                         cudaFuncAttributeMaxDynamicSharedMemorySize, SM1);
    cudaFuncSetAttribute(mma1_gemm<false, OUT_HALF, true>,
                         cudaFuncAttributeMaxDynamicSharedMemorySize, SM1);
    cudaFuncSetAttribute(mma1_gemm<false, OUT_SLOT, false>,
                         cudaFuncAttributeMaxDynamicSharedMemorySize, SM1);

    const dim3 tb(256);
    const dim3 tb1(128);
    const dim3 gR(RHM / BN, NTOK / BM, 1);
    const dim3 gHE(HM / BN, NTOK / BM, EM);    // 16 x 128 x 8
    const dim3 gOE(DM / BN, NTOK / BM, EM);    // 4 x 128 x 8

    // ---- splits first (launches 0-4) so launch 5 is a GEMM (ncu -s 5) ----
    split_kernel<<<512, tb>>>(x, xh, xl, (long)NTOK * DM);
    split_kernel<<<512, tb>>>(r_in_w, wh + WT_RIN, wl + WT_RIN, 512L * 1024L);
    split_kernel<<<512, tb>>>(rs_w1, wh + WT_RS1, wl + WT_RS1, 1024L * 1024L);
    split_kernel<<<512, tb>>>(rs_w2, wh + WT_RS2, wl + WT_RS2, 1024L * 1024L);
    split_kernel<<<512, tb>>>(rs_w3, wh + WT_RS3, wl + WT_RS3, 1024L * 1024L);

    // ---- router (3-term fp16) ----
    mma3_gemm<OUT_SPLIT, false><<<gR, tb, SM3>>>(
        xh, xl, wh + WT_RIN, wl + WT_RIN, r_in_b, b1h, b1l, nullptr,
        nullptr, nullptr, DM, RHM);
    mma3_gemm<OUT_SPLIT, false><<<gR, tb, SM3>>>(
        b1h, b1l, wh + WT_RS1, wl + WT_RS1, rs_b1, b2h, b2l, nullptr,
        nullptr, nullptr, RHM, RHM);
    mma3_gemm<OUT_SPLIT, true><<<gR, tb, SM3>>>(
        b1h, b1l, wh + WT_RS2, wl + WT_RS2, rs_b2, b3h, b3l, nullptr,
        b2h, b2l, RHM, RHM);
    mma3_gemm<OUT_F32, false><<<gR, tb, SM3>>>(
        b3h, b3l, wh + WT_RS3, wl + WT_RS3, rs_b3, nullptr, nullptr, f32buf,
        nullptr, nullptr, RHM, RHM);
    logits_kernel<<<NTOK, tb>>>(f32buf, r_out_w, r_out_b, logits);
    topk_kernel<<<NTOK / 256, tb>>>(logits, maskb);
    compact_kernel<<<EM, tb>>>(maskb, idx, cnt);

    // ---- expert weight converts ----
    cvt_kernel<<<1024, tb>>>(e_in_w, wh + WT_EIN, 8L * 512L * 2048L);
    cvt_kernel<<<2048, tb>>>(es_w1, wh + WT_ES1, 8L * 2048L * 2048L);
    cvt_kernel<<<2048, tb>>>(es_w2, wh + WT_ES2, 8L * 2048L * 2048L);
    cvt_kernel<<<2048, tb>>>(es_w3, wh + WT_ES3, 8L * 2048L * 2048L);
    cvt_kernel<<<1024, tb>>>(e_out_w, wh + WT_EOUT, 8L * 2048L * 512L);

    // ---- experts: 5 z-batched launches (all 8 experts concurrent) ----
    const long NH = (long)NTOK * HM;
    mma1_gemm<true, OUT_HALF, false><<<gHE, tb1, SM1>>>(
        xh, wh + WT_EIN, e_in_b, e1, nullptr, nullptr,
        DM, HM, cnt, idx, nullptr,
        0, (long)DM * HM, HM, NH, 1.f);
    mma1_gemm<false, OUT_HALF, false><<<gHE, tb1, SM1>>>(
        e1, wh + WT_ES1, es_b1, e2, nullptr, nullptr,
        HM, HM, cnt, nullptr, nullptr,
        NH, (long)HM * HM, HM, NH, 1.f);
    mma1_gemm<false, OUT_HALF, true><<<gHE, tb1, SM1>>>(
        e1, wh + WT_ES2, es_b2, e3, nullptr, e2,
        HM, HM, cnt, nullptr, nullptr,
        NH, (long)HM * HM, HM, NH, 1.f);
    mma1_gemm<false, OUT_HALF, false><<<gHE, tb1, SM1>>>(
        e3, wh + WT_ES3, es_b3, e2, nullptr, nullptr,
        HM, HM, cnt, nullptr, nullptr,
        NH, (long)HM * HM, HM, NH, 1.f);
    mma1_gemm<false, OUT_SLOT, false><<<gOE, tb1, SM1>>>(
        e2, wh + WT_EOUT, e_out_b, nullptr, out4, nullptr,
        HM, DM, cnt, idx, maskb,
        NH, (long)HM * DM, DM, 0, 1.f / EM);

    // ---- deterministic 4-slot reduction ----
    reduce_kernel<<<1024, tb>>>(out4, out);
}